// round 5
// baseline (speedup 1.0000x reference)
#include <cuda_runtime.h>
#include <math.h>

#define HH 240
#define WW 320
#define HWP (HH*WW)
#define BB 4
#define CIN 64
#define COUT 24
#define HS 120
#define WS 160
#define NUMK 8

// ---- scratch (static device globals: allowed; no allocation) ----
__device__ float  g_oa[BB*COUT*HWP];     // conv output (only ch 16..23 aff_raw consumed by fused)
__device__ float2 g_off2[BB*NUMK*HWP];   // packed offsets: [b][k][P] = (dy, dx)
__device__ float  g_fea[BB*8*HWP];       // upsampled features CHW
__device__ float  g_feahwc[BB*HWP*8];    // upsampled features HWC
__device__ float  g_U[CIN*16*COUT];      // Winograd-transformed weights [ci][p][co]

__device__ __forceinline__ float tanh_fast(float x) {
    float y;
    asm("tanh.approx.f32 %0, %1;" : "=f"(y) : "f"(x));
    return y;
}

// ============================================================================
// bilinear with zeros padding (matches reference _bilinear_zeros)
// ============================================================================
__device__ __forceinline__ float bilin0(const float* __restrict__ img, float x, float y,
                                        int Hi, int Wi) {
    float xf = floorf(x), yf = floorf(y);
    float wx = x - xf, wy = y - yf;
    int x0 = (int)xf, y0 = (int)yf;
    int x1 = x0 + 1, y1 = y0 + 1;

    bool xv0 = (x0 >= 0) && (x0 <= Wi - 1);
    bool xv1 = (x1 >= 0) && (x1 <= Wi - 1);
    bool yv0 = (y0 >= 0) && (y0 <= Hi - 1);
    bool yv1 = (y1 >= 0) && (y1 <= Hi - 1);

    int xc0 = min(max(x0, 0), Wi - 1);
    int xc1 = min(max(x1, 0), Wi - 1);
    int yc0 = min(max(y0, 0), Hi - 1);
    int yc1 = min(max(y1, 0), Hi - 1);

    float v00 = (xv0 && yv0) ? img[yc0 * Wi + xc0] : 0.0f;
    float v10 = (xv1 && yv0) ? img[yc0 * Wi + xc1] : 0.0f;
    float v01 = (xv0 && yv1) ? img[yc1 * Wi + xc0] : 0.0f;
    float v11 = (xv1 && yv1) ? img[yc1 * Wi + xc1] : 0.0f;

    return v00 * ((1.0f - wy) * (1.0f - wx))
         + v10 * ((1.0f - wy) * wx)
         + v01 * (wy * (1.0f - wx))
         + v11 * (wy * wx);
}

// ============================================================================
// Kernel 1: 2x bilinear upsample of tgtimg_fea + zero out ch 8/9 of offset_full
// ============================================================================
__global__ void upsample_kernel(const float* __restrict__ tgt, float* __restrict__ out) {
    int idx = blockIdx.x * blockDim.x + threadIdx.x;
    if (idx >= BB * HWP) return;
    int b = idx / HWP;
    int P = idx - b * HWP;
    int y = P / WW, x = P - (P / WW) * WW;

    // zero reference-offset channels 8,9 of offset_full
    out[((size_t)b * 18 + 8) * HWP + P] = 0.0f;
    out[((size_t)b * 18 + 9) * HWP + P] = 0.0f;

    int ty = y >> 1, tx = x >> 1;
    int y0, y1, x0, x1;
    float wy0, wy1, wx0, wx1;
    if (y & 1) { y0 = ty; y1 = min(ty + 1, HS - 1); wy0 = 0.75f; wy1 = 0.25f; }
    else       { y0 = max(ty - 1, 0); y1 = ty;      wy0 = 0.25f; wy1 = 0.75f; }
    if (x & 1) { x0 = tx; x1 = min(tx + 1, WS - 1); wx0 = 0.75f; wx1 = 0.25f; }
    else       { x0 = max(tx - 1, 0); x1 = tx;      wx0 = 0.25f; wx1 = 0.75f; }

    const float* base = tgt + b * 8 * HS * WS;
    #pragma unroll
    for (int c = 0; c < 8; c++) {
        const float* pl = base + c * HS * WS;
        float r0 = wx0 * pl[y0 * WS + x0] + wx1 * pl[y0 * WS + x1];
        float r1 = wx0 * pl[y1 * WS + x0] + wx1 * pl[y1 * WS + x1];
        float v = wy0 * r0 + wy1 * r1;
        g_fea[(b * 8 + c) * HWP + P] = v;
        g_feahwc[(b * HWP + P) * 8 + c] = v;
    }
}

// ============================================================================
// Kernel 2: Winograd F(2,3) weight transform U = G g G^T  ->  g_U[ci][p][co]
// ============================================================================
__global__ void wino_weights_kernel(const float* __restrict__ wgt) {
    int t = blockIdx.x * blockDim.x + threadIdx.x;
    if (t >= CIN * COUT) return;
    int ci = t / COUT;
    int co = t - ci * COUT;

    float g[9];
    #pragma unroll
    for (int r = 0; r < 9; r++) g[r] = __ldg(wgt + ((size_t)co * CIN + ci) * 9 + r);

    // q = G g   (4x3)
    float q[4][3];
    #pragma unroll
    for (int c = 0; c < 3; c++) {
        float g0 = g[c], g1 = g[3 + c], g2 = g[6 + c];
        q[0][c] = g0;
        q[1][c] = 0.5f * (g0 + g1 + g2);
        q[2][c] = 0.5f * (g0 - g1 + g2);
        q[3][c] = g2;
    }
    // U = q G^T  (4x4)
    #pragma unroll
    for (int i = 0; i < 4; i++) {
        float v0 = q[i][0], v1 = q[i][1], v2 = q[i][2];
        float u0 = v0;
        float u1 = 0.5f * (v0 + v1 + v2);
        float u2 = 0.5f * (v0 - v1 + v2);
        float u3 = v2;
        g_U[((ci * 16 + i * 4 + 0) * COUT) + co] = u0;
        g_U[((ci * 16 + i * 4 + 1) * COUT) + co] = u1;
        g_U[((ci * 16 + i * 4 + 2) * COUT) + co] = u2;
        g_U[((ci * 16 + i * 4 + 3) * COUT) + co] = u3;
    }
}

// ============================================================================
// Kernel 3: Winograd F(2x2,3x3) conv 64->24 + bias.
// Block covers 8x4 output tiles (16x8 px). 256 threads.
//   per ci-group of 4: 128 threads do V = Bt d B into sV; then all threads run
//   the 16 independent element-GEMMs with acc[8 tiles][6 co] registers.
// Epilogue: M -> smem, Y = At M A, bias, write offsets (out + g_off2) and
// aff_raw (g_oa ch 16..23).
// smem: sV[4][16][33] (pad 33: conflict-free) + sM[32][24][18] (pad 18)
// ============================================================================
#define SV_ELEMS (4*16*33)
#define SM_ELEMS (32*24*18)
#define WINO_SMEM ((SV_ELEMS + SM_ELEMS) * 4)

__global__ __launch_bounds__(256) void conv_wino_kernel(
    const float* __restrict__ gin, const float* __restrict__ bias,
    float* __restrict__ out) {
    extern __shared__ float smem[];
    float* sV = smem;               // [ciq][p][tile(33)]
    float* sM = smem + SV_ELEMS;    // [tile][co][p(18)]

    int tid = threadIdx.x;
    int p  = tid & 15;
    int cg = (tid >> 4) & 3;
    int tq = tid >> 6;
    int bx = blockIdx.x, by = blockIdx.y, b = blockIdx.z;

    float acc[8][6];
    #pragma unroll
    for (int i = 0; i < 8; i++)
        #pragma unroll
        for (int c = 0; c < 6; c++) acc[i][c] = 0.0f;

    const float* gb = gin + (size_t)b * CIN * HWP;

    for (int g4 = 0; g4 < 16; g4++) {
        __syncthreads();
        if (tid < 128) {
            int tile = tid & 31, ciq = tid >> 5;
            int ci = g4 * 4 + ciq;
            int tx = tile & 7, ty = tile >> 3;
            int gx0 = bx * 16 + tx * 2 - 1;
            int gy0 = by * 8 + ty * 2 - 1;
            const float* pl = gb + (size_t)ci * HWP;

            float d[4][4];
            if (gx0 >= 0 && gx0 + 3 < WW && gy0 >= 0 && gy0 + 3 < HH) {
                #pragma unroll
                for (int r = 0; r < 4; r++)
                    #pragma unroll
                    for (int c = 0; c < 4; c++)
                        d[r][c] = __ldg(pl + (gy0 + r) * WW + gx0 + c);
            } else {
                #pragma unroll
                for (int r = 0; r < 4; r++)
                    #pragma unroll
                    for (int c = 0; c < 4; c++) {
                        int yy = gy0 + r, xx = gx0 + c;
                        d[r][c] = (yy >= 0 && yy < HH && xx >= 0 && xx < WW)
                                  ? __ldg(pl + yy * WW + xx) : 0.0f;
                    }
            }
            // e = Bt d (column transform)
            float e[4][4];
            #pragma unroll
            for (int j = 0; j < 4; j++) {
                e[0][j] = d[0][j] - d[2][j];
                e[1][j] = d[1][j] + d[2][j];
                e[2][j] = d[2][j] - d[1][j];
                e[3][j] = d[1][j] - d[3][j];
            }
            // V = e B (row transform)
            #pragma unroll
            for (int i = 0; i < 4; i++) {
                float v0 = e[i][0] - e[i][2];
                float v1 = e[i][1] + e[i][2];
                float v2 = e[i][2] - e[i][1];
                float v3 = e[i][1] - e[i][3];
                sV[(ciq * 16 + i * 4 + 0) * 33 + tile] = v0;
                sV[(ciq * 16 + i * 4 + 1) * 33 + tile] = v1;
                sV[(ciq * 16 + i * 4 + 2) * 33 + tile] = v2;
                sV[(ciq * 16 + i * 4 + 3) * 33 + tile] = v3;
            }
        }
        __syncthreads();

        #pragma unroll
        for (int ciq = 0; ciq < 4; ciq++) {
            int ci = g4 * 4 + ciq;
            float Vv[8];
            #pragma unroll
            for (int i = 0; i < 8; i++)
                Vv[i] = sV[(ciq * 16 + p) * 33 + tq * 8 + i];
            const float* Up = g_U + ((size_t)ci * 16 + p) * COUT + cg * 6;
            float Uu[6];
            #pragma unroll
            for (int c = 0; c < 6; c++) Uu[c] = __ldg(Up + c);
            #pragma unroll
            for (int c = 0; c < 6; c++)
                #pragma unroll
                for (int i = 0; i < 8; i++)
                    acc[i][c] = fmaf(Vv[i], Uu[c], acc[i][c]);
        }
    }

    // ---- M -> smem ----
    __syncthreads();
    #pragma unroll
    for (int i = 0; i < 8; i++)
        #pragma unroll
        for (int c = 0; c < 6; c++)
            sM[((tq * 8 + i) * 24 + cg * 6 + c) * 18 + p] = acc[i][c];
    __syncthreads();

    // ---- epilogue: Y = At M A, bias, stores ----
    for (int it = tid; it < 384; it += 256) {
        int tile = it & 31;
        int cop = it >> 5;               // 0..11 -> co pair (2cop, 2cop+1)
        int tx = tile & 7, ty = tile >> 3;
        int gx = bx * 16 + tx * 2;
        int gy = by * 8 + ty * 2;
        int pix = gy * WW + gx;

        float y2[2][2][2];
        #pragma unroll
        for (int s = 0; s < 2; s++) {
            int co = cop * 2 + s;
            float m[16];
            #pragma unroll
            for (int q = 0; q < 16; q++) m[q] = sM[(tile * 24 + co) * 18 + q];
            float r0[4], r1[4];
            #pragma unroll
            for (int j = 0; j < 4; j++) {
                r0[j] = m[j] + m[4 + j] + m[8 + j];
                r1[j] = m[4 + j] - m[8 + j] - m[12 + j];
            }
            float bv = __ldg(bias + co);
            y2[s][0][0] = r0[0] + r0[1] + r0[2] + bv;
            y2[s][0][1] = r0[1] - r0[2] - r0[3] + bv;
            y2[s][1][0] = r1[0] + r1[1] + r1[2] + bv;
            y2[s][1][1] = r1[1] - r1[2] - r1[3] + bv;

            if (co >= 16) {
                float* oa = g_oa + ((size_t)b * COUT + co) * HWP + pix;
                oa[0] = y2[s][0][0]; oa[1] = y2[s][0][1];
                oa[WW] = y2[s][1][0]; oa[WW + 1] = y2[s][1][1];
            } else {
                int oc = (co < 8) ? co : co + 2;
                float* o = out + ((size_t)b * 18 + oc) * HWP + pix;
                o[0] = y2[s][0][0]; o[1] = y2[s][0][1];
                o[WW] = y2[s][1][0]; o[WW + 1] = y2[s][1][1];
            }
        }
        if (cop < 8) {
            float2* op = g_off2 + ((size_t)b * NUMK + cop) * HWP + pix;
            op[0]      = make_float2(y2[0][0][0], y2[1][0][0]);
            op[1]      = make_float2(y2[0][0][1], y2[1][0][1]);
            op[WW]     = make_float2(y2[0][1][0], y2[1][1][0]);
            op[WW + 1] = make_float2(y2[0][1][1], y2[1][1][1]);
        }
    }
}

// ============================================================================
// Kernel 4: fused cos-affinity + confidence + TGASS + softmax (as R3).
// ============================================================================
__global__ void fused_kernel(const float* __restrict__ gtconf,
                             const float* __restrict__ ascp,
                             float* __restrict__ out) {
    int Xg = blockIdx.x * 256 + threadIdx.x;
    int b = Xg / (8 * HWP);
    int X = Xg - b * (8 * HWP);
    int c = X / HWP;
    int P2 = X - c * HWP;
    int P = X >> 3;
    int m = X & 7;
    int i2 = P2 / WW, j2 = P2 - i2 * WW;

    const float2* off_b = g_off2 + (size_t)b * NUMK * HWP;
    const float*  oa_b  = g_oa + (size_t)b * COUT * HWP;
    const float*  feac  = g_fea + ((size_t)b * 8 + c) * HWP;
    float fv = g_feahwc[((size_t)b * HWP + P) * 8 + m];

    float v[8];
    #pragma unroll
    for (int k = 0; k < 8; k++) {
        float2 o = off_b[(size_t)k * HWP + P2];        // (dy, dx)
        float base = (k < 4) ? (float)i2 : (float)j2;  // faithful to ref's repeat bug
        v[k] = fv * bilin0(feac, o.x + base, o.y + base, HH, WW);
    }

    int l = threadIdx.x & 31;
    #pragma unroll
    for (int d = 4; d >= 1; d >>= 1) {
        #pragma unroll
        for (int k = 0; k < 8; k++) {
            float o = __shfl_xor_sync(0xffffffffu, v[k], d);
            if (((k ^ l) & d) == 0) v[k] += o;
        }
    }
    float cw = v[m];

    int i = P / WW, j = P - i * WW;
    float araw = oa_b[(size_t)(16 + m) * HWP + P];
    float2 od = off_b[(size_t)m * HWP + P];            // (dy, dx)
    const float* gc = gtconf + (size_t)b * HWP;
    float conf = bilin0(gc, od.y + (float)j, od.x + (float)i, HH, WW);

    float asc = __ldg(ascp);
    float aff = __fdividef(tanh_fast(araw * cw), asc + 1e-8f);
    aff = aff * conf;

    float s = fabsf(aff);
    s += __shfl_xor_sync(0xffffffffu, s, 1);
    s += __shfl_xor_sync(0xffffffffu, s, 2);
    s += __shfl_xor_sync(0xffffffffu, s, 4);
    float denom = fmaxf(s + 1e-4f, 1.0f);
    float an = __fdividef(aff, denom);

    float t = an;
    t += __shfl_xor_sync(0xffffffffu, t, 1);
    t += __shfl_xor_sync(0xffffffffu, t, 2);
    t += __shfl_xor_sync(0xffffffffu, t, 4);
    float ref = 1.0f - t;

    float mx = an;
    mx = fmaxf(mx, __shfl_xor_sync(0xffffffffu, mx, 1));
    mx = fmaxf(mx, __shfl_xor_sync(0xffffffffu, mx, 2));
    mx = fmaxf(mx, __shfl_xor_sync(0xffffffffu, mx, 4));
    mx = fmaxf(mx, ref);

    float e  = __expf(an - mx);
    float er = __expf(ref - mx);
    float se = e;
    se += __shfl_xor_sync(0xffffffffu, se, 1);
    se += __shfl_xor_sync(0xffffffffu, se, 2);
    se += __shfl_xor_sync(0xffffffffu, se, 4);
    se += er;
    float inv = __fdividef(1.0f, se);

    float* outa = out + (size_t)BB * 18 * HWP + (size_t)b * 9 * HWP;
    int oc = (m < 4) ? m : m + 1;
    outa[(size_t)oc * HWP + P] = e * inv;
    if (m == 0) outa[(size_t)4 * HWP + P] = er * inv;
}

// ============================================================================
extern "C" void kernel_launch(void* const* d_in, const int* in_sizes, int n_in,
                              void* d_out, int out_size) {
    const float* guidance = (const float*)d_in[0];
    const float* gtconf   = (const float*)d_in[1];
    const float* tgt      = (const float*)d_in[2];
    const float* convw    = (const float*)d_in[3];
    const float* convb    = (const float*)d_in[4];
    const float* asc      = (const float*)d_in[5];
    float* out = (float*)d_out;

    cudaFuncSetAttribute(conv_wino_kernel,
                         cudaFuncAttributeMaxDynamicSharedMemorySize, WINO_SMEM);

    upsample_kernel<<<(BB * HWP + 255) / 256, 256>>>(tgt, out);
    wino_weights_kernel<<<(CIN * COUT + 255) / 256, 256>>>(convw);
    conv_wino_kernel<<<dim3(WW / 16, HH / 8, BB), 256, WINO_SMEM>>>(guidance, convb, out);
    fused_kernel<<<(BB * 8 * HWP) / 256, 256>>>(gtconf, asc, out);
}

// round 6
// speedup vs baseline: 1.1453x; 1.1453x over previous
#include <cuda_runtime.h>
#include <math.h>

#define HH 240
#define WW 320
#define HWP (HH*WW)
#define BB 4
#define CIN 64
#define COUT 24
#define HS 120
#define WS 160
#define NUMK 8

// ---- scratch (static device globals: allowed; no allocation) ----
__device__ float  g_oa[BB*COUT*HWP];     // conv output (only ch 16..23 aff_raw consumed by fused)
__device__ float2 g_off2[BB*NUMK*HWP];   // packed offsets: [b][k][P] = (dy, dx)
__device__ float  g_fea[BB*8*HWP];       // upsampled features CHW
__device__ float  g_feahwc[BB*HWP*8];    // upsampled features HWC
__device__ float  g_U[CIN*16*COUT];      // Winograd-transformed weights [ci][p][co]

__device__ __forceinline__ float tanh_fast(float x) {
    float y;
    asm("tanh.approx.f32 %0, %1;" : "=f"(y) : "f"(x));
    return y;
}

// ============================================================================
// bilinear with zeros padding (matches reference _bilinear_zeros)
// ============================================================================
__device__ __forceinline__ float bilin0(const float* __restrict__ img, float x, float y,
                                        int Hi, int Wi) {
    float xf = floorf(x), yf = floorf(y);
    float wx = x - xf, wy = y - yf;
    int x0 = (int)xf, y0 = (int)yf;
    int x1 = x0 + 1, y1 = y0 + 1;

    bool xv0 = (x0 >= 0) && (x0 <= Wi - 1);
    bool xv1 = (x1 >= 0) && (x1 <= Wi - 1);
    bool yv0 = (y0 >= 0) && (y0 <= Hi - 1);
    bool yv1 = (y1 >= 0) && (y1 <= Hi - 1);

    int xc0 = min(max(x0, 0), Wi - 1);
    int xc1 = min(max(x1, 0), Wi - 1);
    int yc0 = min(max(y0, 0), Hi - 1);
    int yc1 = min(max(y1, 0), Hi - 1);

    float v00 = (xv0 && yv0) ? img[yc0 * Wi + xc0] : 0.0f;
    float v10 = (xv1 && yv0) ? img[yc0 * Wi + xc1] : 0.0f;
    float v01 = (xv0 && yv1) ? img[yc1 * Wi + xc0] : 0.0f;
    float v11 = (xv1 && yv1) ? img[yc1 * Wi + xc1] : 0.0f;

    return v00 * ((1.0f - wy) * (1.0f - wx))
         + v10 * ((1.0f - wy) * wx)
         + v01 * (wy * (1.0f - wx))
         + v11 * (wy * wx);
}

// ============================================================================
// Kernel 1: 2x bilinear upsample of tgtimg_fea + zero out ch 8/9 of offset_full
// ============================================================================
__global__ void upsample_kernel(const float* __restrict__ tgt, float* __restrict__ out) {
    int idx = blockIdx.x * blockDim.x + threadIdx.x;
    if (idx >= BB * HWP) return;
    int b = idx / HWP;
    int P = idx - b * HWP;
    int y = P / WW, x = P - (P / WW) * WW;

    out[((size_t)b * 18 + 8) * HWP + P] = 0.0f;
    out[((size_t)b * 18 + 9) * HWP + P] = 0.0f;

    int ty = y >> 1, tx = x >> 1;
    int y0, y1, x0, x1;
    float wy0, wy1, wx0, wx1;
    if (y & 1) { y0 = ty; y1 = min(ty + 1, HS - 1); wy0 = 0.75f; wy1 = 0.25f; }
    else       { y0 = max(ty - 1, 0); y1 = ty;      wy0 = 0.25f; wy1 = 0.75f; }
    if (x & 1) { x0 = tx; x1 = min(tx + 1, WS - 1); wx0 = 0.75f; wx1 = 0.25f; }
    else       { x0 = max(tx - 1, 0); x1 = tx;      wx0 = 0.25f; wx1 = 0.75f; }

    const float* base = tgt + b * 8 * HS * WS;
    #pragma unroll
    for (int c = 0; c < 8; c++) {
        const float* pl = base + c * HS * WS;
        float r0 = wx0 * pl[y0 * WS + x0] + wx1 * pl[y0 * WS + x1];
        float r1 = wx0 * pl[y1 * WS + x0] + wx1 * pl[y1 * WS + x1];
        float v = wy0 * r0 + wy1 * r1;
        g_fea[(b * 8 + c) * HWP + P] = v;
        g_feahwc[(b * HWP + P) * 8 + c] = v;
    }
}

// ============================================================================
// Kernel 2: Winograd F(2,3) weight transform U = G g G^T  ->  g_U[ci][p][co]
// ============================================================================
__global__ void wino_weights_kernel(const float* __restrict__ wgt) {
    int t = blockIdx.x * blockDim.x + threadIdx.x;
    if (t >= CIN * COUT) return;
    int ci = t / COUT;
    int co = t - ci * COUT;

    float g[9];
    #pragma unroll
    for (int r = 0; r < 9; r++) g[r] = __ldg(wgt + ((size_t)co * CIN + ci) * 9 + r);

    float q[4][3];
    #pragma unroll
    for (int c = 0; c < 3; c++) {
        float g0 = g[c], g1 = g[3 + c], g2 = g[6 + c];
        q[0][c] = g0;
        q[1][c] = 0.5f * (g0 + g1 + g2);
        q[2][c] = 0.5f * (g0 - g1 + g2);
        q[3][c] = g2;
    }
    #pragma unroll
    for (int i = 0; i < 4; i++) {
        float v0 = q[i][0], v1 = q[i][1], v2 = q[i][2];
        g_U[((ci * 16 + i * 4 + 0) * COUT) + co] = v0;
        g_U[((ci * 16 + i * 4 + 1) * COUT) + co] = 0.5f * (v0 + v1 + v2);
        g_U[((ci * 16 + i * 4 + 2) * COUT) + co] = 0.5f * (v0 - v1 + v2);
        g_U[((ci * 16 + i * 4 + 3) * COUT) + co] = v2;
    }
}

// ============================================================================
// Kernel 3: Winograd F(2x2,3x3) conv 64->24 + bias.
// Block covers 8x4 output tiles (16x8 px). 256 threads, >=3 CTAs/SM forced.
// 8 outer groups of 8 input channels:
//   transform: ALL 256 threads (32 tiles x 8 ci = 256 tasks) do V = Bt d B -> sV
//   GEMM: acc[8 tiles][6 co] registers over the 16 Winograd points
// Two-pass epilogue through halved sM: Y = At M A, bias, stores.
// smem: sV[8][16][33] + sM[32][12][18] = 44.5 KB
// ============================================================================
#define SV_ELEMS (8*16*33)
#define SM_ELEMS (32*12*18)
#define WINO_SMEM ((SV_ELEMS + SM_ELEMS) * 4)

__global__ __launch_bounds__(256, 3) void conv_wino_kernel(
    const float* __restrict__ gin, const float* __restrict__ bias,
    float* __restrict__ out) {
    extern __shared__ float smem[];
    float* sV = smem;               // [ciq][p][tile(33)]
    float* sM = smem + SV_ELEMS;    // [tile][co12][p(18)]

    int tid = threadIdx.x;
    int p  = tid & 15;
    int cg = (tid >> 4) & 3;
    int tq = tid >> 6;
    int bx = blockIdx.x, by = blockIdx.y, b = blockIdx.z;

    float acc[8][6];
    #pragma unroll
    for (int i = 0; i < 8; i++)
        #pragma unroll
        for (int c = 0; c < 6; c++) acc[i][c] = 0.0f;

    const float* gb = gin + (size_t)b * CIN * HWP;

    // transform-task coords (one (tile, ci) per thread)
    int ttile = tid & 31;
    int tciq  = tid >> 5;
    int ttx = ttile & 7, tty = ttile >> 3;
    int tgx0 = bx * 16 + ttx * 2 - 1;
    int tgy0 = by * 8 + tty * 2 - 1;
    bool interior = (tgx0 >= 0 && tgx0 + 3 < WW && tgy0 >= 0 && tgy0 + 3 < HH);

    for (int g8 = 0; g8 < 8; g8++) {
        __syncthreads();
        {
            int ci = g8 * 8 + tciq;
            const float* pl = gb + (size_t)ci * HWP;
            float d[4][4];
            if (interior) {
                #pragma unroll
                for (int r = 0; r < 4; r++)
                    #pragma unroll
                    for (int c = 0; c < 4; c++)
                        d[r][c] = __ldg(pl + (tgy0 + r) * WW + tgx0 + c);
            } else {
                #pragma unroll
                for (int r = 0; r < 4; r++)
                    #pragma unroll
                    for (int c = 0; c < 4; c++) {
                        int yy = tgy0 + r, xx = tgx0 + c;
                        d[r][c] = (yy >= 0 && yy < HH && xx >= 0 && xx < WW)
                                  ? __ldg(pl + yy * WW + xx) : 0.0f;
                    }
            }
            float e[4][4];
            #pragma unroll
            for (int j = 0; j < 4; j++) {
                e[0][j] = d[0][j] - d[2][j];
                e[1][j] = d[1][j] + d[2][j];
                e[2][j] = d[2][j] - d[1][j];
                e[3][j] = d[1][j] - d[3][j];
            }
            #pragma unroll
            for (int i = 0; i < 4; i++) {
                sV[(tciq * 16 + i * 4 + 0) * 33 + ttile] = e[i][0] - e[i][2];
                sV[(tciq * 16 + i * 4 + 1) * 33 + ttile] = e[i][1] + e[i][2];
                sV[(tciq * 16 + i * 4 + 2) * 33 + ttile] = e[i][2] - e[i][1];
                sV[(tciq * 16 + i * 4 + 3) * 33 + ttile] = e[i][1] - e[i][3];
            }
        }
        __syncthreads();

        #pragma unroll
        for (int ciq = 0; ciq < 8; ciq++) {
            int ci = g8 * 8 + ciq;
            float Vv[8];
            #pragma unroll
            for (int i = 0; i < 8; i++)
                Vv[i] = sV[(ciq * 16 + p) * 33 + tq * 8 + i];
            const float* Up = g_U + ((size_t)ci * 16 + p) * COUT + cg * 6;
            float Uu[6];
            #pragma unroll
            for (int c = 0; c < 6; c++) Uu[c] = __ldg(Up + c);
            #pragma unroll
            for (int c = 0; c < 6; c++)
                #pragma unroll
                for (int i = 0; i < 8; i++)
                    acc[i][c] = fmaf(Vv[i], Uu[c], acc[i][c]);
        }
    }

    // ---- two-pass epilogue: Y = At M A, bias, stores ----
    #pragma unroll
    for (int pp = 0; pp < 2; pp++) {
        __syncthreads();
        if ((cg >> 1) == pp) {
            #pragma unroll
            for (int i = 0; i < 8; i++)
                #pragma unroll
                for (int c = 0; c < 6; c++)
                    sM[((tq * 8 + i) * 12 + (cg & 1) * 6 + c) * 18 + p] = acc[i][c];
        }
        __syncthreads();

        if (tid < 192) {
            int tile = tid & 31;
            int cop = tid >> 5;              // 0..5
            int tx = tile & 7, ty = tile >> 3;
            int gx = bx * 16 + tx * 2;
            int gy = by * 8 + ty * 2;
            int pix = gy * WW + gx;

            float y2[2][2][2];
            #pragma unroll
            for (int s = 0; s < 2; s++) {
                int col = cop * 2 + s;       // local 0..11
                int co = pp * 12 + col;
                float m[16];
                #pragma unroll
                for (int q = 0; q < 16; q++) m[q] = sM[(tile * 12 + col) * 18 + q];
                float r0[4], r1[4];
                #pragma unroll
                for (int j = 0; j < 4; j++) {
                    r0[j] = m[j] + m[4 + j] + m[8 + j];
                    r1[j] = m[4 + j] - m[8 + j] - m[12 + j];
                }
                float bv = __ldg(bias + co);
                y2[s][0][0] = r0[0] + r0[1] + r0[2] + bv;
                y2[s][0][1] = r0[1] - r0[2] - r0[3] + bv;
                y2[s][1][0] = r1[0] + r1[1] + r1[2] + bv;
                y2[s][1][1] = r1[1] - r1[2] - r1[3] + bv;

                if (co >= 16) {
                    float* oa = g_oa + ((size_t)b * COUT + co) * HWP + pix;
                    oa[0] = y2[s][0][0]; oa[1] = y2[s][0][1];
                    oa[WW] = y2[s][1][0]; oa[WW + 1] = y2[s][1][1];
                } else {
                    int oc = (co < 8) ? co : co + 2;
                    float* o = out + ((size_t)b * 18 + oc) * HWP + pix;
                    o[0] = y2[s][0][0]; o[1] = y2[s][0][1];
                    o[WW] = y2[s][1][0]; o[WW + 1] = y2[s][1][1];
                }
            }
            int co0g = pp * 12 + cop * 2;
            if (co0g < 16) {
                float2* op = g_off2 + ((size_t)b * NUMK + (co0g >> 1)) * HWP + pix;
                op[0]      = make_float2(y2[0][0][0], y2[1][0][0]);
                op[1]      = make_float2(y2[0][0][1], y2[1][0][1]);
                op[WW]     = make_float2(y2[0][1][0], y2[1][1][0]);
                op[WW + 1] = make_float2(y2[0][1][1], y2[1][1][1]);
            }
        }
    }
}

// ============================================================================
// Kernel 4: fused cos-affinity + confidence + TGASS + softmax.
// ============================================================================
__global__ void fused_kernel(const float* __restrict__ gtconf,
                             const float* __restrict__ ascp,
                             float* __restrict__ out) {
    int Xg = blockIdx.x * 256 + threadIdx.x;
    int b = Xg / (8 * HWP);
    int X = Xg - b * (8 * HWP);
    int c = X / HWP;
    int P2 = X - c * HWP;
    int P = X >> 3;
    int m = X & 7;
    int i2 = P2 / WW, j2 = P2 - i2 * WW;

    const float2* off_b = g_off2 + (size_t)b * NUMK * HWP;
    const float*  oa_b  = g_oa + (size_t)b * COUT * HWP;
    const float*  feac  = g_fea + ((size_t)b * 8 + c) * HWP;
    float fv = g_feahwc[((size_t)b * HWP + P) * 8 + m];

    float v[8];
    #pragma unroll
    for (int k = 0; k < 8; k++) {
        float2 o = off_b[(size_t)k * HWP + P2];        // (dy, dx)
        float base = (k < 4) ? (float)i2 : (float)j2;  // faithful to ref's repeat bug
        v[k] = fv * bilin0(feac, o.x + base, o.y + base, HH, WW);
    }

    int l = threadIdx.x & 31;
    #pragma unroll
    for (int d = 4; d >= 1; d >>= 1) {
        #pragma unroll
        for (int k = 0; k < 8; k++) {
            float o = __shfl_xor_sync(0xffffffffu, v[k], d);
            if (((k ^ l) & d) == 0) v[k] += o;
        }
    }
    float cw = v[m];

    int i = P / WW, j = P - i * WW;
    float araw = oa_b[(size_t)(16 + m) * HWP + P];
    float2 od = off_b[(size_t)m * HWP + P];            // (dy, dx)
    const float* gc = gtconf + (size_t)b * HWP;
    float conf = bilin0(gc, od.y + (float)j, od.x + (float)i, HH, WW);

    float asc = __ldg(ascp);
    float aff = __fdividef(tanh_fast(araw * cw), asc + 1e-8f);
    aff = aff * conf;

    float s = fabsf(aff);
    s += __shfl_xor_sync(0xffffffffu, s, 1);
    s += __shfl_xor_sync(0xffffffffu, s, 2);
    s += __shfl_xor_sync(0xffffffffu, s, 4);
    float denom = fmaxf(s + 1e-4f, 1.0f);
    float an = __fdividef(aff, denom);

    float t = an;
    t += __shfl_xor_sync(0xffffffffu, t, 1);
    t += __shfl_xor_sync(0xffffffffu, t, 2);
    t += __shfl_xor_sync(0xffffffffu, t, 4);
    float ref = 1.0f - t;

    float mx = an;
    mx = fmaxf(mx, __shfl_xor_sync(0xffffffffu, mx, 1));
    mx = fmaxf(mx, __shfl_xor_sync(0xffffffffu, mx, 2));
    mx = fmaxf(mx, __shfl_xor_sync(0xffffffffu, mx, 4));
    mx = fmaxf(mx, ref);

    float e  = __expf(an - mx);
    float er = __expf(ref - mx);
    float se = e;
    se += __shfl_xor_sync(0xffffffffu, se, 1);
    se += __shfl_xor_sync(0xffffffffu, se, 2);
    se += __shfl_xor_sync(0xffffffffu, se, 4);
    se += er;
    float inv = __fdividef(1.0f, se);

    float* outa = out + (size_t)BB * 18 * HWP + (size_t)b * 9 * HWP;
    int oc = (m < 4) ? m : m + 1;
    outa[(size_t)oc * HWP + P] = e * inv;
    if (m == 0) outa[(size_t)4 * HWP + P] = er * inv;
}

// ============================================================================
extern "C" void kernel_launch(void* const* d_in, const int* in_sizes, int n_in,
                              void* d_out, int out_size) {
    const float* guidance = (const float*)d_in[0];
    const float* gtconf   = (const float*)d_in[1];
    const float* tgt      = (const float*)d_in[2];
    const float* convw    = (const float*)d_in[3];
    const float* convb    = (const float*)d_in[4];
    const float* asc      = (const float*)d_in[5];
    float* out = (float*)d_out;

    cudaFuncSetAttribute(conv_wino_kernel,
                         cudaFuncAttributeMaxDynamicSharedMemorySize, WINO_SMEM);

    upsample_kernel<<<(BB * HWP + 255) / 256, 256>>>(tgt, out);
    wino_weights_kernel<<<(CIN * COUT + 255) / 256, 256>>>(convw);
    conv_wino_kernel<<<dim3(WW / 16, HH / 8, BB), 256, WINO_SMEM>>>(guidance, convb, out);
    fused_kernel<<<(BB * 8 * HWP) / 256, 256>>>(gtconf, asc, out);
}

// round 7
// speedup vs baseline: 1.1517x; 1.0056x over previous
#include <cuda_runtime.h>
#include <math.h>

#define HH 240
#define WW 320
#define HWP (HH*WW)
#define BB 4
#define CIN 64
#define COUT 24
#define HS 120
#define WS 160
#define NUMK 8

// ---- scratch (static device globals: allowed; no allocation) ----
__device__ float  g_oa[BB*COUT*HWP];     // conv output (only ch 16..23 aff_raw consumed by fused)
__device__ float2 g_off2[BB*NUMK*HWP];   // packed offsets: [b][k][P] = (dy, dx)
__device__ float  g_fea[BB*8*HWP];       // upsampled features CHW
__device__ float  g_feahwc[BB*HWP*8];    // upsampled features HWC
__device__ float  g_U[CIN*16*COUT];      // Winograd-transformed weights [ci][p][co]

__device__ __forceinline__ float tanh_fast(float x) {
    float y;
    asm("tanh.approx.f32 %0, %1;" : "=f"(y) : "f"(x));
    return y;
}

// ============================================================================
// bilinear with zeros padding (matches reference _bilinear_zeros)
// ============================================================================
__device__ __forceinline__ float bilin0(const float* __restrict__ img, float x, float y,
                                        int Hi, int Wi) {
    float xf = floorf(x), yf = floorf(y);
    float wx = x - xf, wy = y - yf;
    int x0 = (int)xf, y0 = (int)yf;
    int x1 = x0 + 1, y1 = y0 + 1;

    bool xv0 = (x0 >= 0) && (x0 <= Wi - 1);
    bool xv1 = (x1 >= 0) && (x1 <= Wi - 1);
    bool yv0 = (y0 >= 0) && (y0 <= Hi - 1);
    bool yv1 = (y1 >= 0) && (y1 <= Hi - 1);

    int xc0 = min(max(x0, 0), Wi - 1);
    int xc1 = min(max(x1, 0), Wi - 1);
    int yc0 = min(max(y0, 0), Hi - 1);
    int yc1 = min(max(y1, 0), Hi - 1);

    float v00 = (xv0 && yv0) ? img[yc0 * Wi + xc0] : 0.0f;
    float v10 = (xv1 && yv0) ? img[yc0 * Wi + xc1] : 0.0f;
    float v01 = (xv0 && yv1) ? img[yc1 * Wi + xc0] : 0.0f;
    float v11 = (xv1 && yv1) ? img[yc1 * Wi + xc1] : 0.0f;

    return v00 * ((1.0f - wy) * (1.0f - wx))
         + v10 * ((1.0f - wy) * wx)
         + v01 * (wy * (1.0f - wx))
         + v11 * (wy * wx);
}

// ============================================================================
// Kernel 1: 2x bilinear upsample of tgtimg_fea + zero out ch 8/9 of offset_full
// ============================================================================
__global__ void upsample_kernel(const float* __restrict__ tgt, float* __restrict__ out) {
    int idx = blockIdx.x * blockDim.x + threadIdx.x;
    if (idx >= BB * HWP) return;
    int b = idx / HWP;
    int P = idx - b * HWP;
    int y = P / WW, x = P - (P / WW) * WW;

    out[((size_t)b * 18 + 8) * HWP + P] = 0.0f;
    out[((size_t)b * 18 + 9) * HWP + P] = 0.0f;

    int ty = y >> 1, tx = x >> 1;
    int y0, y1, x0, x1;
    float wy0, wy1, wx0, wx1;
    if (y & 1) { y0 = ty; y1 = min(ty + 1, HS - 1); wy0 = 0.75f; wy1 = 0.25f; }
    else       { y0 = max(ty - 1, 0); y1 = ty;      wy0 = 0.25f; wy1 = 0.75f; }
    if (x & 1) { x0 = tx; x1 = min(tx + 1, WS - 1); wx0 = 0.75f; wx1 = 0.25f; }
    else       { x0 = max(tx - 1, 0); x1 = tx;      wx0 = 0.25f; wx1 = 0.75f; }

    const float* base = tgt + b * 8 * HS * WS;
    #pragma unroll
    for (int c = 0; c < 8; c++) {
        const float* pl = base + c * HS * WS;
        float r0 = wx0 * pl[y0 * WS + x0] + wx1 * pl[y0 * WS + x1];
        float r1 = wx0 * pl[y1 * WS + x0] + wx1 * pl[y1 * WS + x1];
        float v = wy0 * r0 + wy1 * r1;
        g_fea[(b * 8 + c) * HWP + P] = v;
        g_feahwc[(b * HWP + P) * 8 + c] = v;
    }
}

// ============================================================================
// Kernel 2: Winograd F(2,3) weight transform U = G g G^T  ->  g_U[ci][p][co]
// ============================================================================
__global__ void wino_weights_kernel(const float* __restrict__ wgt) {
    int t = blockIdx.x * blockDim.x + threadIdx.x;
    if (t >= CIN * COUT) return;
    int ci = t / COUT;
    int co = t - ci * COUT;

    float g[9];
    #pragma unroll
    for (int r = 0; r < 9; r++) g[r] = __ldg(wgt + ((size_t)co * CIN + ci) * 9 + r);

    float q[4][3];
    #pragma unroll
    for (int c = 0; c < 3; c++) {
        float g0 = g[c], g1 = g[3 + c], g2 = g[6 + c];
        q[0][c] = g0;
        q[1][c] = 0.5f * (g0 + g1 + g2);
        q[2][c] = 0.5f * (g0 - g1 + g2);
        q[3][c] = g2;
    }
    #pragma unroll
    for (int i = 0; i < 4; i++) {
        float v0 = q[i][0], v1 = q[i][1], v2 = q[i][2];
        g_U[((ci * 16 + i * 4 + 0) * COUT) + co] = v0;
        g_U[((ci * 16 + i * 4 + 1) * COUT) + co] = 0.5f * (v0 + v1 + v2);
        g_U[((ci * 16 + i * 4 + 2) * COUT) + co] = 0.5f * (v0 - v1 + v2);
        g_U[((ci * 16 + i * 4 + 3) * COUT) + co] = v2;
    }
}

// ============================================================================
// Kernel 3: Winograd F(2x2,3x3) conv 64->24 + bias.
// Block covers 8x4 output tiles (16x8 px). 256 threads, >=3 CTAs/SM forced.
// 8 outer groups of 8 input channels:
//   transform: ALL 256 threads (32 tiles x 8 ci) do V = Bt d B -> sV,
//              AND coalesced-copy the group's U slab into sU (stride-25 rows:
//              conflict-free for the 16p x 2cg lane pattern).
//   GEMM: acc[8 tiles][6 co]; inner loop all-LDS (no gathers), FMA-bound.
// Two-pass epilogue through sM (aliases sU): Y = At M A, bias, stores.
// smem: sV[8*16*33] + max(sM[32*12*18], sU[8*16*25]) = 44.5 KB
// ============================================================================
#define SV_ELEMS (8*16*33)
#define SM_ELEMS (32*12*18)
#define SU_ELEMS (8*16*25)
#define WINO_SMEM ((SV_ELEMS + SM_ELEMS) * 4)

__global__ __launch_bounds__(256, 3) void conv_wino_kernel(
    const float* __restrict__ gin, const float* __restrict__ bias,
    float* __restrict__ out) {
    extern __shared__ float smem[];
    float* sV = smem;               // [ciq][p][tile(33)]
    float* sM = smem + SV_ELEMS;    // epilogue: [tile][co12][p(18)]
    float* sU = smem + SV_ELEMS;    // mainloop: [ciq*16+p][co(25)]  (aliases sM)

    int tid = threadIdx.x;
    int p  = tid & 15;
    int cg = (tid >> 4) & 3;
    int tq = tid >> 6;
    int bx = blockIdx.x, by = blockIdx.y, b = blockIdx.z;

    float acc[8][6];
    #pragma unroll
    for (int i = 0; i < 8; i++)
        #pragma unroll
        for (int c = 0; c < 6; c++) acc[i][c] = 0.0f;

    const float* gb = gin + (size_t)b * CIN * HWP;

    // transform-task coords (one (tile, ci) per thread)
    int ttile = tid & 31;
    int tciq  = tid >> 5;
    int ttx = ttile & 7, tty = ttile >> 3;
    int tgx0 = bx * 16 + ttx * 2 - 1;
    int tgy0 = by * 8 + tty * 2 - 1;
    bool interior = (tgx0 >= 0 && tgx0 + 3 < WW && tgy0 >= 0 && tgy0 + 3 < HH);

    for (int g8 = 0; g8 < 8; g8++) {
        __syncthreads();
        // ---- stage U slab for this group: coalesced 3072-float copy ----
        {
            const float* src = g_U + g8 * (8 * 16 * 24);
            #pragma unroll
            for (int k = 0; k < 12; k++) {
                int idx = tid + k * 256;          // 0..3071
                int row = idx / 24;               // ciq*16 + p
                int co  = idx - row * 24;
                sU[row * 25 + co] = __ldg(src + idx);
            }
        }
        // ---- input transform ----
        {
            int ci = g8 * 8 + tciq;
            const float* pl = gb + (size_t)ci * HWP;
            float d[4][4];
            if (interior) {
                #pragma unroll
                for (int r = 0; r < 4; r++)
                    #pragma unroll
                    for (int c = 0; c < 4; c++)
                        d[r][c] = __ldg(pl + (tgy0 + r) * WW + tgx0 + c);
            } else {
                #pragma unroll
                for (int r = 0; r < 4; r++)
                    #pragma unroll
                    for (int c = 0; c < 4; c++) {
                        int yy = tgy0 + r, xx = tgx0 + c;
                        d[r][c] = (yy >= 0 && yy < HH && xx >= 0 && xx < WW)
                                  ? __ldg(pl + yy * WW + xx) : 0.0f;
                    }
            }
            float e[4][4];
            #pragma unroll
            for (int j = 0; j < 4; j++) {
                e[0][j] = d[0][j] - d[2][j];
                e[1][j] = d[1][j] + d[2][j];
                e[2][j] = d[2][j] - d[1][j];
                e[3][j] = d[1][j] - d[3][j];
            }
            #pragma unroll
            for (int i = 0; i < 4; i++) {
                sV[(tciq * 16 + i * 4 + 0) * 33 + ttile] = e[i][0] - e[i][2];
                sV[(tciq * 16 + i * 4 + 1) * 33 + ttile] = e[i][1] + e[i][2];
                sV[(tciq * 16 + i * 4 + 2) * 33 + ttile] = e[i][2] - e[i][1];
                sV[(tciq * 16 + i * 4 + 3) * 33 + ttile] = e[i][1] - e[i][3];
            }
        }
        __syncthreads();

        // ---- element GEMM: all-LDS inner loop ----
        #pragma unroll
        for (int ciq = 0; ciq < 8; ciq++) {
            float Vv[8];
            #pragma unroll
            for (int i = 0; i < 8; i++)
                Vv[i] = sV[(ciq * 16 + p) * 33 + tq * 8 + i];
            const float* Up = sU + (ciq * 16 + p) * 25 + cg * 6;
            float Uu[6];
            #pragma unroll
            for (int c = 0; c < 6; c++) Uu[c] = Up[c];
            #pragma unroll
            for (int c = 0; c < 6; c++)
                #pragma unroll
                for (int i = 0; i < 8; i++)
                    acc[i][c] = fmaf(Vv[i], Uu[c], acc[i][c]);
        }
    }

    // ---- two-pass epilogue: Y = At M A, bias, stores ----
    #pragma unroll
    for (int pp = 0; pp < 2; pp++) {
        __syncthreads();
        if ((cg >> 1) == pp) {
            #pragma unroll
            for (int i = 0; i < 8; i++)
                #pragma unroll
                for (int c = 0; c < 6; c++)
                    sM[((tq * 8 + i) * 12 + (cg & 1) * 6 + c) * 18 + p] = acc[i][c];
        }
        __syncthreads();

        if (tid < 192) {
            int tile = tid & 31;
            int cop = tid >> 5;              // 0..5
            int tx = tile & 7, ty = tile >> 3;
            int gx = bx * 16 + tx * 2;
            int gy = by * 8 + ty * 2;
            int pix = gy * WW + gx;

            float y2[2][2][2];
            #pragma unroll
            for (int s = 0; s < 2; s++) {
                int col = cop * 2 + s;       // local 0..11
                int co = pp * 12 + col;
                float m[16];
                #pragma unroll
                for (int q = 0; q < 16; q++) m[q] = sM[(tile * 12 + col) * 18 + q];
                float r0[4], r1[4];
                #pragma unroll
                for (int j = 0; j < 4; j++) {
                    r0[j] = m[j] + m[4 + j] + m[8 + j];
                    r1[j] = m[4 + j] - m[8 + j] - m[12 + j];
                }
                float bv = __ldg(bias + co);
                y2[s][0][0] = r0[0] + r0[1] + r0[2] + bv;
                y2[s][0][1] = r0[1] - r0[2] - r0[3] + bv;
                y2[s][1][0] = r1[0] + r1[1] + r1[2] + bv;
                y2[s][1][1] = r1[1] - r1[2] - r1[3] + bv;

                if (co >= 16) {
                    float* oa = g_oa + ((size_t)b * COUT + co) * HWP + pix;
                    oa[0] = y2[s][0][0]; oa[1] = y2[s][0][1];
                    oa[WW] = y2[s][1][0]; oa[WW + 1] = y2[s][1][1];
                } else {
                    int oc = (co < 8) ? co : co + 2;
                    float* o = out + ((size_t)b * 18 + oc) * HWP + pix;
                    o[0] = y2[s][0][0]; o[1] = y2[s][0][1];
                    o[WW] = y2[s][1][0]; o[WW + 1] = y2[s][1][1];
                }
            }
            int co0g = pp * 12 + cop * 2;
            if (co0g < 16) {
                float2* op = g_off2 + ((size_t)b * NUMK + (co0g >> 1)) * HWP + pix;
                op[0]      = make_float2(y2[0][0][0], y2[1][0][0]);
                op[1]      = make_float2(y2[0][0][1], y2[1][0][1]);
                op[WW]     = make_float2(y2[0][1][0], y2[1][1][0]);
                op[WW + 1] = make_float2(y2[0][1][1], y2[1][1][1]);
            }
        }
    }
}

// ============================================================================
// Kernel 4: fused cos-affinity + confidence + TGASS + softmax.
// ============================================================================
__global__ void fused_kernel(const float* __restrict__ gtconf,
                             const float* __restrict__ ascp,
                             float* __restrict__ out) {
    int Xg = blockIdx.x * 256 + threadIdx.x;
    int b = Xg / (8 * HWP);
    int X = Xg - b * (8 * HWP);
    int c = X / HWP;
    int P2 = X - c * HWP;
    int P = X >> 3;
    int m = X & 7;
    int i2 = P2 / WW, j2 = P2 - i2 * WW;

    const float2* off_b = g_off2 + (size_t)b * NUMK * HWP;
    const float*  oa_b  = g_oa + (size_t)b * COUT * HWP;
    const float*  feac  = g_fea + ((size_t)b * 8 + c) * HWP;
    float fv = g_feahwc[((size_t)b * HWP + P) * 8 + m];

    float v[8];
    #pragma unroll
    for (int k = 0; k < 8; k++) {
        float2 o = off_b[(size_t)k * HWP + P2];        // (dy, dx)
        float base = (k < 4) ? (float)i2 : (float)j2;  // faithful to ref's repeat bug
        v[k] = fv * bilin0(feac, o.x + base, o.y + base, HH, WW);
    }

    int l = threadIdx.x & 31;
    #pragma unroll
    for (int d = 4; d >= 1; d >>= 1) {
        #pragma unroll
        for (int k = 0; k < 8; k++) {
            float o = __shfl_xor_sync(0xffffffffu, v[k], d);
            if (((k ^ l) & d) == 0) v[k] += o;
        }
    }
    float cw = v[m];

    int i = P / WW, j = P - i * WW;
    float araw = oa_b[(size_t)(16 + m) * HWP + P];
    float2 od = off_b[(size_t)m * HWP + P];            // (dy, dx)
    const float* gc = gtconf + (size_t)b * HWP;
    float conf = bilin0(gc, od.y + (float)j, od.x + (float)i, HH, WW);

    float asc = __ldg(ascp);
    float aff = __fdividef(tanh_fast(araw * cw), asc + 1e-8f);
    aff = aff * conf;

    float s = fabsf(aff);
    s += __shfl_xor_sync(0xffffffffu, s, 1);
    s += __shfl_xor_sync(0xffffffffu, s, 2);
    s += __shfl_xor_sync(0xffffffffu, s, 4);
    float denom = fmaxf(s + 1e-4f, 1.0f);
    float an = __fdividef(aff, denom);

    float t = an;
    t += __shfl_xor_sync(0xffffffffu, t, 1);
    t += __shfl_xor_sync(0xffffffffu, t, 2);
    t += __shfl_xor_sync(0xffffffffu, t, 4);
    float ref = 1.0f - t;

    float mx = an;
    mx = fmaxf(mx, __shfl_xor_sync(0xffffffffu, mx, 1));
    mx = fmaxf(mx, __shfl_xor_sync(0xffffffffu, mx, 2));
    mx = fmaxf(mx, __shfl_xor_sync(0xffffffffu, mx, 4));
    mx = fmaxf(mx, ref);

    float e  = __expf(an - mx);
    float er = __expf(ref - mx);
    float se = e;
    se += __shfl_xor_sync(0xffffffffu, se, 1);
    se += __shfl_xor_sync(0xffffffffu, se, 2);
    se += __shfl_xor_sync(0xffffffffu, se, 4);
    se += er;
    float inv = __fdividef(1.0f, se);

    float* outa = out + (size_t)BB * 18 * HWP + (size_t)b * 9 * HWP;
    int oc = (m < 4) ? m : m + 1;
    outa[(size_t)oc * HWP + P] = e * inv;
    if (m == 0) outa[(size_t)4 * HWP + P] = er * inv;
}

// ============================================================================
extern "C" void kernel_launch(void* const* d_in, const int* in_sizes, int n_in,
                              void* d_out, int out_size) {
    const float* guidance = (const float*)d_in[0];
    const float* gtconf   = (const float*)d_in[1];
    const float* tgt      = (const float*)d_in[2];
    const float* convw    = (const float*)d_in[3];
    const float* convb    = (const float*)d_in[4];
    const float* asc      = (const float*)d_in[5];
    float* out = (float*)d_out;

    cudaFuncSetAttribute(conv_wino_kernel,
                         cudaFuncAttributeMaxDynamicSharedMemorySize, WINO_SMEM);

    upsample_kernel<<<(BB * HWP + 255) / 256, 256>>>(tgt, out);
    wino_weights_kernel<<<(CIN * COUT + 255) / 256, 256>>>(convw);
    conv_wino_kernel<<<dim3(WW / 16, HH / 8, BB), 256, WINO_SMEM>>>(guidance, convb, out);
    fused_kernel<<<(BB * 8 * HWP) / 256, 256>>>(gtconf, asc, out);
}

// round 9
// speedup vs baseline: 1.2597x; 1.0937x over previous
#include <cuda_runtime.h>
#include <math.h>

#define HH 240
#define WW 320
#define HWP (HH*WW)
#define BB 4
#define CIN 64
#define COUT 24
#define HS 120
#define WS 160
#define NUMK 8

// ---- scratch (static device globals: allowed; no allocation) ----
__device__ float  g_oa[BB*COUT*HWP];     // conv output (only ch 16..23 aff_raw consumed by fused)
__device__ float2 g_off2[BB*NUMK*HWP];   // packed offsets: [b][k][P] = (dy, dx)
__device__ float  g_fea[BB*8*HWP];       // upsampled features CHW
__device__ float  g_feahwc[BB*HWP*8];    // upsampled features HWC
__device__ float  g_U[CIN*16*COUT];      // Winograd-transformed weights [ci][p][co]

__device__ __forceinline__ float tanh_fast(float x) {
    float y;
    asm("tanh.approx.f32 %0, %1;" : "=f"(y) : "f"(x));
    return y;
}

// ============================================================================
// bilinear with zeros padding (matches reference _bilinear_zeros)
// ============================================================================
__device__ __forceinline__ float bilin0(const float* __restrict__ img, float x, float y,
                                        int Hi, int Wi) {
    float xf = floorf(x), yf = floorf(y);
    float wx = x - xf, wy = y - yf;
    int x0 = (int)xf, y0 = (int)yf;
    int x1 = x0 + 1, y1 = y0 + 1;

    bool xv0 = (x0 >= 0) && (x0 <= Wi - 1);
    bool xv1 = (x1 >= 0) && (x1 <= Wi - 1);
    bool yv0 = (y0 >= 0) && (y0 <= Hi - 1);
    bool yv1 = (y1 >= 0) && (y1 <= Hi - 1);

    int xc0 = min(max(x0, 0), Wi - 1);
    int xc1 = min(max(x1, 0), Wi - 1);
    int yc0 = min(max(y0, 0), Hi - 1);
    int yc1 = min(max(y1, 0), Hi - 1);

    float v00 = (xv0 && yv0) ? img[yc0 * Wi + xc0] : 0.0f;
    float v10 = (xv1 && yv0) ? img[yc0 * Wi + xc1] : 0.0f;
    float v01 = (xv0 && yv1) ? img[yc1 * Wi + xc0] : 0.0f;
    float v11 = (xv1 && yv1) ? img[yc1 * Wi + xc1] : 0.0f;

    return v00 * ((1.0f - wy) * (1.0f - wx))
         + v10 * ((1.0f - wy) * wx)
         + v01 * (wy * (1.0f - wx))
         + v11 * (wy * wx);
}

// ============================================================================
// Kernel 1: 2x bilinear upsample + zero ch 8/9 of offset_full.
// g_feahwc written as two float4 stores (was 8 strided STG.32).
// ============================================================================
__global__ void upsample_kernel(const float* __restrict__ tgt, float* __restrict__ out) {
    int idx = blockIdx.x * blockDim.x + threadIdx.x;
    if (idx >= BB * HWP) return;
    int b = idx / HWP;
    int P = idx - b * HWP;
    int y = P / WW, x = P - (P / WW) * WW;

    out[((size_t)b * 18 + 8) * HWP + P] = 0.0f;
    out[((size_t)b * 18 + 9) * HWP + P] = 0.0f;

    int ty = y >> 1, tx = x >> 1;
    int y0, y1, x0, x1;
    float wy0, wy1, wx0, wx1;
    if (y & 1) { y0 = ty; y1 = min(ty + 1, HS - 1); wy0 = 0.75f; wy1 = 0.25f; }
    else       { y0 = max(ty - 1, 0); y1 = ty;      wy0 = 0.25f; wy1 = 0.75f; }
    if (x & 1) { x0 = tx; x1 = min(tx + 1, WS - 1); wx0 = 0.75f; wx1 = 0.25f; }
    else       { x0 = max(tx - 1, 0); x1 = tx;      wx0 = 0.25f; wx1 = 0.75f; }

    const float* base = tgt + b * 8 * HS * WS;
    float vv[8];
    #pragma unroll
    for (int c = 0; c < 8; c++) {
        const float* pl = base + c * HS * WS;
        float r0 = wx0 * pl[y0 * WS + x0] + wx1 * pl[y0 * WS + x1];
        float r1 = wx0 * pl[y1 * WS + x0] + wx1 * pl[y1 * WS + x1];
        float v = wy0 * r0 + wy1 * r1;
        g_fea[(b * 8 + c) * HWP + P] = v;
        vv[c] = v;
    }
    float4* dst = (float4*)(g_feahwc + ((size_t)b * HWP + P) * 8);
    dst[0] = make_float4(vv[0], vv[1], vv[2], vv[3]);
    dst[1] = make_float4(vv[4], vv[5], vv[6], vv[7]);
}

// ============================================================================
// Kernel 2: Winograd F(2,3) weight transform U = G g G^T  ->  g_U[ci][p][co]
// ============================================================================
__global__ void wino_weights_kernel(const float* __restrict__ wgt) {
    int t = blockIdx.x * blockDim.x + threadIdx.x;
    if (t >= CIN * COUT) return;
    int ci = t / COUT;
    int co = t - ci * COUT;

    float g[9];
    #pragma unroll
    for (int r = 0; r < 9; r++) g[r] = __ldg(wgt + ((size_t)co * CIN + ci) * 9 + r);

    float q[4][3];
    #pragma unroll
    for (int c = 0; c < 3; c++) {
        float g0 = g[c], g1 = g[3 + c], g2 = g[6 + c];
        q[0][c] = g0;
        q[1][c] = 0.5f * (g0 + g1 + g2);
        q[2][c] = 0.5f * (g0 - g1 + g2);
        q[3][c] = g2;
    }
    #pragma unroll
    for (int i = 0; i < 4; i++) {
        float v0 = q[i][0], v1 = q[i][1], v2 = q[i][2];
        g_U[((ci * 16 + i * 4 + 0) * COUT) + co] = v0;
        g_U[((ci * 16 + i * 4 + 1) * COUT) + co] = 0.5f * (v0 + v1 + v2);
        g_U[((ci * 16 + i * 4 + 2) * COUT) + co] = 0.5f * (v0 - v1 + v2);
        g_U[((ci * 16 + i * 4 + 3) * COUT) + co] = v2;
    }
}

// ---- bounds-checked row load for the input transform ----
__device__ __forceinline__ void load_row4(const float* __restrict__ pl, int yy, int x0,
                                          bool xin, float r[4]) {
    if (yy >= 0 && yy < HH) {
        if (xin) {
            r[0] = __ldg(pl + yy * WW + x0);
            r[1] = __ldg(pl + yy * WW + x0 + 1);
            r[2] = __ldg(pl + yy * WW + x0 + 2);
            r[3] = __ldg(pl + yy * WW + x0 + 3);
        } else {
            #pragma unroll
            for (int c = 0; c < 4; c++) {
                int xx = x0 + c;
                r[c] = (xx >= 0 && xx < WW) ? __ldg(pl + yy * WW + xx) : 0.0f;
            }
        }
    } else {
        r[0] = r[1] = r[2] = r[3] = 0.0f;
    }
}

// ============================================================================
// Kernel 3: Winograd F(2x2,3x3) conv 64->24 + bias.
// Register-lean transform: rows streamed in two pairs so the live set at the
// transform/GEMM boundary is acc(48) + e(16) + 8 row regs ~ 78 regs -> no
// spill under the 3-CTA/SM cap (the R5/R6 versions held d[16]+e[16] and
// spilled accumulators to local memory).
// smem: sV[8*16*33] + max(sM[32*12*18], sU[8*16*25]) = 44.5 KB
// ============================================================================
#define SV_ELEMS (8*16*33)
#define SM_ELEMS (32*12*18)
#define WINO_SMEM ((SV_ELEMS + SM_ELEMS) * 4)

__global__ __launch_bounds__(256, 3) void conv_wino_kernel(
    const float* __restrict__ gin, const float* __restrict__ bias,
    float* __restrict__ out) {
    extern __shared__ float smem[];
    float* sV = smem;               // [ciq][p][tile(33)]
    float* sM = smem + SV_ELEMS;    // epilogue: [tile][co12][p(18)]
    float* sU = smem + SV_ELEMS;    // mainloop: [ciq*16+p][co(25)]  (aliases sM)

    int tid = threadIdx.x;
    int p  = tid & 15;
    int cg = (tid >> 4) & 3;
    int tq = tid >> 6;
    int bx = blockIdx.x, by = blockIdx.y, b = blockIdx.z;

    float acc[8][6];
    #pragma unroll
    for (int i = 0; i < 8; i++)
        #pragma unroll
        for (int c = 0; c < 6; c++) acc[i][c] = 0.0f;

    const float* gb = gin + (size_t)b * CIN * HWP;

    // transform-task coords (one (tile, ci) per thread)
    int ttile = tid & 31;
    int tciq  = tid >> 5;
    int ttx = ttile & 7, tty = ttile >> 3;
    int tgx0 = bx * 16 + ttx * 2 - 1;
    int tgy0 = by * 8 + tty * 2 - 1;
    bool xin = (tgx0 >= 0 && tgx0 + 3 < WW);

    for (int g8 = 0; g8 < 8; g8++) {
        __syncthreads();
        // ---- stage U slab: coalesced 3072-float copy ----
        {
            const float* src = g_U + g8 * (8 * 16 * 24);
            #pragma unroll
            for (int k = 0; k < 12; k++) {
                int idx = tid + k * 256;
                int row = idx / 24;
                int co  = idx - row * 24;
                sU[row * 25 + co] = __ldg(src + idx);
            }
        }
        // ---- input transform (register-lean, row-streamed) ----
        {
            const float* pl = gb + (size_t)(g8 * 8 + tciq) * HWP;
            float e0[4], e1[4], e2[4], e3[4];
            {
                float r0[4], r1[4];
                load_row4(pl, tgy0,     tgx0, xin, r0);
                load_row4(pl, tgy0 + 1, tgx0, xin, r1);
                #pragma unroll
                for (int c = 0; c < 4; c++) { e0[c] = r0[c]; e1[c] = r1[c]; e3[c] = r1[c]; }
            }
            {
                float r2[4], r3[4];
                load_row4(pl, tgy0 + 2, tgx0, xin, r2);
                load_row4(pl, tgy0 + 3, tgx0, xin, r3);
                #pragma unroll
                for (int c = 0; c < 4; c++) {
                    e2[c] = r2[c] - e1[c];   // d2 - d1
                    e1[c] += r2[c];          // d1 + d2
                    e0[c] -= r2[c];          // d0 - d2
                    e3[c] -= r3[c];          // d1 - d3
                }
            }
            // row transform: V row i -> sV
            float* svb = sV + tciq * 16 * 33 + ttile;
            #pragma unroll
            for (int i = 0; i < 4; i++) {
                const float* er = (i == 0) ? e0 : (i == 1) ? e1 : (i == 2) ? e2 : e3;
                svb[(i * 4 + 0) * 33] = er[0] - er[2];
                svb[(i * 4 + 1) * 33] = er[1] + er[2];
                svb[(i * 4 + 2) * 33] = er[2] - er[1];
                svb[(i * 4 + 3) * 33] = er[1] - er[3];
            }
        }
        __syncthreads();

        // ---- element GEMM: all-LDS inner loop ----
        #pragma unroll
        for (int ciq = 0; ciq < 8; ciq++) {
            float Vv[8];
            #pragma unroll
            for (int i = 0; i < 8; i++)
                Vv[i] = sV[(ciq * 16 + p) * 33 + tq * 8 + i];
            const float* Up = sU + (ciq * 16 + p) * 25 + cg * 6;
            float Uu[6];
            #pragma unroll
            for (int c = 0; c < 6; c++) Uu[c] = Up[c];
            #pragma unroll
            for (int c = 0; c < 6; c++)
                #pragma unroll
                for (int i = 0; i < 8; i++)
                    acc[i][c] = fmaf(Vv[i], Uu[c], acc[i][c]);
        }
    }

    // ---- two-pass epilogue: Y = At M A, bias, stores ----
    #pragma unroll
    for (int pp = 0; pp < 2; pp++) {
        __syncthreads();
        if ((cg >> 1) == pp) {
            #pragma unroll
            for (int i = 0; i < 8; i++)
                #pragma unroll
                for (int c = 0; c < 6; c++)
                    sM[((tq * 8 + i) * 12 + (cg & 1) * 6 + c) * 18 + p] = acc[i][c];
        }
        __syncthreads();

        if (tid < 192) {
            int tile = tid & 31;
            int cop = tid >> 5;              // 0..5
            int tx = tile & 7, ty = tile >> 3;
            int gx = bx * 16 + tx * 2;
            int gy = by * 8 + ty * 2;
            int pix = gy * WW + gx;

            float y2[2][2][2];
            #pragma unroll
            for (int s = 0; s < 2; s++) {
                int col = cop * 2 + s;       // local 0..11
                int co = pp * 12 + col;
                float m[16];
                #pragma unroll
                for (int q = 0; q < 16; q++) m[q] = sM[(tile * 12 + col) * 18 + q];
                float r0[4], r1[4];
                #pragma unroll
                for (int j = 0; j < 4; j++) {
                    r0[j] = m[j] + m[4 + j] + m[8 + j];
                    r1[j] = m[4 + j] - m[8 + j] - m[12 + j];
                }
                float bv = __ldg(bias + co);
                y2[s][0][0] = r0[0] + r0[1] + r0[2] + bv;
                y2[s][0][1] = r0[1] - r0[2] - r0[3] + bv;
                y2[s][1][0] = r1[0] + r1[1] + r1[2] + bv;
                y2[s][1][1] = r1[1] - r1[2] - r1[3] + bv;

                if (co >= 16) {
                    float* oa = g_oa + ((size_t)b * COUT + co) * HWP + pix;
                    oa[0] = y2[s][0][0]; oa[1] = y2[s][0][1];
                    oa[WW] = y2[s][1][0]; oa[WW + 1] = y2[s][1][1];
                } else {
                    int oc = (co < 8) ? co : co + 2;
                    float* o = out + ((size_t)b * 18 + oc) * HWP + pix;
                    o[0] = y2[s][0][0]; o[1] = y2[s][0][1];
                    o[WW] = y2[s][1][0]; o[WW + 1] = y2[s][1][1];
                }
            }
            int co0g = pp * 12 + cop * 2;
            if (co0g < 16) {
                float2* op = g_off2 + ((size_t)b * NUMK + (co0g >> 1)) * HWP + pix;
                op[0]      = make_float2(y2[0][0][0], y2[1][0][0]);
                op[1]      = make_float2(y2[0][0][1], y2[1][0][1]);
                op[WW]     = make_float2(y2[0][1][0], y2[1][1][0]);
                op[WW + 1] = make_float2(y2[0][1][1], y2[1][1][1]);
            }
        }
    }
}

// ============================================================================
// Kernel 4: fused cos-affinity + confidence + TGASS + softmax.
// ============================================================================
__global__ void fused_kernel(const float* __restrict__ gtconf,
                             const float* __restrict__ ascp,
                             float* __restrict__ out) {
    int Xg = blockIdx.x * 256 + threadIdx.x;
    int b = Xg / (8 * HWP);
    int X = Xg - b * (8 * HWP);
    int c = X / HWP;
    int P2 = X - c * HWP;
    int P = X >> 3;
    int m = X & 7;
    int i2 = P2 / WW, j2 = P2 - i2 * WW;

    const float2* off_b = g_off2 + (size_t)b * NUMK * HWP;
    const float*  oa_b  = g_oa + (size_t)b * COUT * HWP;
    const float*  feac  = g_fea + ((size_t)b * 8 + c) * HWP;
    float fv = g_feahwc[((size_t)b * HWP + P) * 8 + m];

    float v[8];
    #pragma unroll
    for (int k = 0; k < 8; k++) {
        float2 o = off_b[(size_t)k * HWP + P2];        // (dy, dx)
        float base = (k < 4) ? (float)i2 : (float)j2;  // faithful to ref's repeat bug
        v[k] = fv * bilin0(feac, o.x + base, o.y + base, HH, WW);
    }

    int l = threadIdx.x & 31;
    #pragma unroll
    for (int d = 4; d >= 1; d >>= 1) {
        #pragma unroll
        for (int k = 0; k < 8; k++) {
            float o = __shfl_xor_sync(0xffffffffu, v[k], d);
            if (((k ^ l) & d) == 0) v[k] += o;
        }
    }
    float cw = v[m];

    int i = P / WW, j = P - i * WW;
    float araw = oa_b[(size_t)(16 + m) * HWP + P];
    float2 od = off_b[(size_t)m * HWP + P];            // (dy, dx)
    const float* gc = gtconf + (size_t)b * HWP;
    float conf = bilin0(gc, od.y + (float)j, od.x + (float)i, HH, WW);

    float asc = __ldg(ascp);
    float aff = __fdividef(tanh_fast(araw * cw), asc + 1e-8f);
    aff = aff * conf;

    float s = fabsf(aff);
    s += __shfl_xor_sync(0xffffffffu, s, 1);
    s += __shfl_xor_sync(0xffffffffu, s, 2);
    s += __shfl_xor_sync(0xffffffffu, s, 4);
    float denom = fmaxf(s + 1e-4f, 1.0f);
    float an = __fdividef(aff, denom);

    float t = an;
    t += __shfl_xor_sync(0xffffffffu, t, 1);
    t += __shfl_xor_sync(0xffffffffu, t, 2);
    t += __shfl_xor_sync(0xffffffffu, t, 4);
    float ref = 1.0f - t;

    float mx = an;
    mx = fmaxf(mx, __shfl_xor_sync(0xffffffffu, mx, 1));
    mx = fmaxf(mx, __shfl_xor_sync(0xffffffffu, mx, 2));
    mx = fmaxf(mx, __shfl_xor_sync(0xffffffffu, mx, 4));
    mx = fmaxf(mx, ref);

    float e  = __expf(an - mx);
    float er = __expf(ref - mx);
    float se = e;
    se += __shfl_xor_sync(0xffffffffu, se, 1);
    se += __shfl_xor_sync(0xffffffffu, se, 2);
    se += __shfl_xor_sync(0xffffffffu, se, 4);
    se += er;
    float inv = __fdividef(1.0f, se);

    float* outa = out + (size_t)BB * 18 * HWP + (size_t)b * 9 * HWP;
    int oc = (m < 4) ? m : m + 1;
    outa[(size_t)oc * HWP + P] = e * inv;
    if (m == 0) outa[(size_t)4 * HWP + P] = er * inv;
}

// ============================================================================
extern "C" void kernel_launch(void* const* d_in, const int* in_sizes, int n_in,
                              void* d_out, int out_size) {
    const float* guidance = (const float*)d_in[0];
    const float* gtconf   = (const float*)d_in[1];
    const float* tgt      = (const float*)d_in[2];
    const float* convw    = (const float*)d_in[3];
    const float* convb    = (const float*)d_in[4];
    const float* asc      = (const float*)d_in[5];
    float* out = (float*)d_out;

    cudaFuncSetAttribute(conv_wino_kernel,
                         cudaFuncAttributeMaxDynamicSharedMemorySize, WINO_SMEM);

    upsample_kernel<<<(BB * HWP + 255) / 256, 256>>>(tgt, out);
    wino_weights_kernel<<<(CIN * COUT + 255) / 256, 256>>>(convw);
    conv_wino_kernel<<<dim3(WW / 16, HH / 8, BB), 256, WINO_SMEM>>>(guidance, convb, out);
    fused_kernel<<<(BB * 8 * HWP) / 256, 256>>>(gtconf, asc, out);
}

// round 11
// speedup vs baseline: 1.3846x; 1.0991x over previous
#include <cuda_runtime.h>
#include <math.h>

#define HH 240
#define WW 320
#define HWP (HH*WW)
#define BB 4
#define CIN 64
#define COUT 24
#define HS 120
#define WS 160
#define NUMK 8

// ---- scratch (static device globals: allowed; no allocation) ----
__device__ float  g_oa[BB*COUT*HWP];     // conv output (only ch 16..23 aff_raw consumed by fused)
__device__ float2 g_off2[BB*NUMK*HWP];   // packed offsets: [b][k][P] = (dy, dx)
__device__ float  g_fea[BB*8*HWP];       // upsampled features CHW
__device__ float  g_feahwc[BB*HWP*8];    // upsampled features HWC
__device__ float  g_U[CIN*16*COUT];      // Winograd-transformed weights [ci][p][co]

__device__ __forceinline__ float tanh_fast(float x) {
    float y;
    asm("tanh.approx.f32 %0, %1;" : "=f"(y) : "f"(x));
    return y;
}

// ============================================================================
// bilinear with zeros padding (matches reference _bilinear_zeros)
// ============================================================================
__device__ __forceinline__ float bilin0(const float* __restrict__ img, float x, float y,
                                        int Hi, int Wi) {
    float xf = floorf(x), yf = floorf(y);
    float wx = x - xf, wy = y - yf;
    int x0 = (int)xf, y0 = (int)yf;
    int x1 = x0 + 1, y1 = y0 + 1;

    bool xv0 = (x0 >= 0) && (x0 <= Wi - 1);
    bool xv1 = (x1 >= 0) && (x1 <= Wi - 1);
    bool yv0 = (y0 >= 0) && (y0 <= Hi - 1);
    bool yv1 = (y1 >= 0) && (y1 <= Hi - 1);

    int xc0 = min(max(x0, 0), Wi - 1);
    int xc1 = min(max(x1, 0), Wi - 1);
    int yc0 = min(max(y0, 0), Hi - 1);
    int yc1 = min(max(y1, 0), Hi - 1);

    float v00 = (xv0 && yv0) ? img[yc0 * Wi + xc0] : 0.0f;
    float v10 = (xv1 && yv0) ? img[yc0 * Wi + xc1] : 0.0f;
    float v01 = (xv0 && yv1) ? img[yc1 * Wi + xc0] : 0.0f;
    float v11 = (xv1 && yv1) ? img[yc1 * Wi + xc1] : 0.0f;

    return v00 * ((1.0f - wy) * (1.0f - wx))
         + v10 * ((1.0f - wy) * wx)
         + v01 * (wy * (1.0f - wx))
         + v11 * (wy * wx);
}

// ============================================================================
// Kernel 1: 2x bilinear upsample + zero ch 8/9 of offset_full.
// ============================================================================
__global__ void upsample_kernel(const float* __restrict__ tgt, float* __restrict__ out) {
    int idx = blockIdx.x * blockDim.x + threadIdx.x;
    if (idx >= BB * HWP) return;
    int b = idx / HWP;
    int P = idx - b * HWP;
    int y = P / WW, x = P - (P / WW) * WW;

    out[((size_t)b * 18 + 8) * HWP + P] = 0.0f;
    out[((size_t)b * 18 + 9) * HWP + P] = 0.0f;

    int ty = y >> 1, tx = x >> 1;
    int y0, y1, x0, x1;
    float wy0, wy1, wx0, wx1;
    if (y & 1) { y0 = ty; y1 = min(ty + 1, HS - 1); wy0 = 0.75f; wy1 = 0.25f; }
    else       { y0 = max(ty - 1, 0); y1 = ty;      wy0 = 0.25f; wy1 = 0.75f; }
    if (x & 1) { x0 = tx; x1 = min(tx + 1, WS - 1); wx0 = 0.75f; wx1 = 0.25f; }
    else       { x0 = max(tx - 1, 0); x1 = tx;      wx0 = 0.25f; wx1 = 0.75f; }

    const float* base = tgt + b * 8 * HS * WS;
    float vv[8];
    #pragma unroll
    for (int c = 0; c < 8; c++) {
        const float* pl = base + c * HS * WS;
        float r0 = wx0 * pl[y0 * WS + x0] + wx1 * pl[y0 * WS + x1];
        float r1 = wx0 * pl[y1 * WS + x0] + wx1 * pl[y1 * WS + x1];
        float v = wy0 * r0 + wy1 * r1;
        g_fea[(b * 8 + c) * HWP + P] = v;
        vv[c] = v;
    }
    float4* dst = (float4*)(g_feahwc + ((size_t)b * HWP + P) * 8);
    dst[0] = make_float4(vv[0], vv[1], vv[2], vv[3]);
    dst[1] = make_float4(vv[4], vv[5], vv[6], vv[7]);
}

// ============================================================================
// Kernel 2: Winograd F(2,3) weight transform U = G g G^T  ->  g_U[ci][p][co]
// ============================================================================
__global__ void wino_weights_kernel(const float* __restrict__ wgt) {
    int t = blockIdx.x * blockDim.x + threadIdx.x;
    if (t >= CIN * COUT) return;
    int ci = t / COUT;
    int co = t - ci * COUT;

    float g[9];
    #pragma unroll
    for (int r = 0; r < 9; r++) g[r] = __ldg(wgt + ((size_t)co * CIN + ci) * 9 + r);

    float q[4][3];
    #pragma unroll
    for (int c = 0; c < 3; c++) {
        float g0 = g[c], g1 = g[3 + c], g2 = g[6 + c];
        q[0][c] = g0;
        q[1][c] = 0.5f * (g0 + g1 + g2);
        q[2][c] = 0.5f * (g0 - g1 + g2);
        q[3][c] = g2;
    }
    #pragma unroll
    for (int i = 0; i < 4; i++) {
        float v0 = q[i][0], v1 = q[i][1], v2 = q[i][2];
        g_U[((ci * 16 + i * 4 + 0) * COUT) + co] = v0;
        g_U[((ci * 16 + i * 4 + 1) * COUT) + co] = 0.5f * (v0 + v1 + v2);
        g_U[((ci * 16 + i * 4 + 2) * COUT) + co] = 0.5f * (v0 - v1 + v2);
        g_U[((ci * 16 + i * 4 + 3) * COUT) + co] = v2;
    }
}

// ============================================================================
// Kernel 3: Winograd F(2x2,3x3) conv 64->24 + bias. Software-pipelined:
// raw 4x4 guidance tile for group g+1 is loaded into registers right after
// the second sync and stays in flight UNDER the GEMM of group g.
// FIX vs R9: row validity carried in rok[] (bool), NOT encoded as ro==-1 —
// the sentinel collided with the legitimate offset -1 at (yy=0, tgx0=-1),
// zeroing a partially-valid boundary row (caused the 3.9e-3 rel_err).
// smem: sV[8*16*33] + max(sM[32*12*18], sU[8*16*25]) = 44.5 KB
// ============================================================================
#define SV_ELEMS (8*16*33)
#define SM_ELEMS (32*12*18)
#define WINO_SMEM ((SV_ELEMS + SM_ELEMS) * 4)

__global__ __launch_bounds__(256, 2) void conv_wino_kernel(
    const float* __restrict__ gin, const float* __restrict__ bias,
    float* __restrict__ out) {
    extern __shared__ float smem[];
    float* sV = smem;               // [ciq][p][tile(33)]
    float* sM = smem + SV_ELEMS;    // epilogue: [tile][co12][p(18)]
    float* sU = smem + SV_ELEMS;    // mainloop: [ciq*16+p][co(25)]  (aliases sM)

    int tid = threadIdx.x;
    int p  = tid & 15;
    int cg = (tid >> 4) & 3;
    int tq = tid >> 6;
    int bx = blockIdx.x, by = blockIdx.y, b = blockIdx.z;

    float acc[8][6];
    #pragma unroll
    for (int i = 0; i < 8; i++)
        #pragma unroll
        for (int c = 0; c < 6; c++) acc[i][c] = 0.0f;

    const float* gb = gin + (size_t)b * CIN * HWP;

    // transform-task coords (one (tile, ci) per thread)
    int ttile = tid & 31;
    int tciq  = tid >> 5;
    int ttx = ttile & 7, tty = ttile >> 3;
    int tgx0 = bx * 16 + ttx * 2 - 1;
    int tgy0 = by * 8 + tty * 2 - 1;
    bool xin = (tgx0 >= 0 && tgx0 + 3 < WW);

    // row offsets + separate validity flags (no sentinel aliasing!)
    int ro[4];
    bool rok[4];
    bool cok[4];
    #pragma unroll
    for (int rr = 0; rr < 4; rr++) {
        int yy = tgy0 + rr;
        rok[rr] = (yy >= 0 && yy < HH);
        ro[rr] = yy * WW + tgx0;
    }
    #pragma unroll
    for (int c = 0; c < 4; c++) {
        int xx = tgx0 + c;
        cok[c] = (xx >= 0 && xx < WW);
    }

    // raw prefetch registers (held across the GEMM of the previous group)
    float r[4][4];
    {
        const float* pl = gb + (size_t)tciq * HWP;      // group 0
        #pragma unroll
        for (int rr = 0; rr < 4; rr++) {
            if (rok[rr]) {
                if (xin) {
                    r[rr][0] = __ldg(pl + ro[rr]);
                    r[rr][1] = __ldg(pl + ro[rr] + 1);
                    r[rr][2] = __ldg(pl + ro[rr] + 2);
                    r[rr][3] = __ldg(pl + ro[rr] + 3);
                } else {
                    #pragma unroll
                    for (int c = 0; c < 4; c++)
                        r[rr][c] = cok[c] ? __ldg(pl + ro[rr] + c) : 0.0f;
                }
            } else {
                r[rr][0] = r[rr][1] = r[rr][2] = r[rr][3] = 0.0f;
            }
        }
    }

    for (int g8 = 0; g8 < 8; g8++) {
        // ---- fold raw rows -> e (ALU only; r becomes dead) ----
        float e0[4], e1[4], e2[4], e3[4];
        #pragma unroll
        for (int c = 0; c < 4; c++) {
            e0[c] = r[0][c] - r[2][c];
            e1[c] = r[1][c] + r[2][c];
            e2[c] = r[2][c] - r[1][c];
            e3[c] = r[1][c] - r[3][c];
        }

        __syncthreads();   // GEMM of g8-1 done reading sV/sU

        // ---- STS transform rows into sV ----
        {
            float* svb = sV + tciq * 16 * 33 + ttile;
            #pragma unroll
            for (int i = 0; i < 4; i++) {
                const float* er = (i == 0) ? e0 : (i == 1) ? e1 : (i == 2) ? e2 : e3;
                svb[(i * 4 + 0) * 33] = er[0] - er[2];
                svb[(i * 4 + 1) * 33] = er[1] + er[2];
                svb[(i * 4 + 2) * 33] = er[2] - er[1];
                svb[(i * 4 + 3) * 33] = er[1] - er[3];
            }
        }
        // ---- stage U slab: coalesced 3072-float copy (L2-resident) ----
        {
            const float* src = g_U + g8 * (8 * 16 * 24);
            #pragma unroll
            for (int k = 0; k < 12; k++) {
                int idx = tid + k * 256;
                int row = idx / 24;
                int co  = idx - row * 24;
                sU[row * 25 + co] = __ldg(src + idx);
            }
        }
        __syncthreads();

        // ---- issue prefetch for group g8+1 (in flight during GEMM) ----
        if (g8 < 7) {
            const float* pl = gb + (size_t)((g8 + 1) * 8 + tciq) * HWP;
            #pragma unroll
            for (int rr = 0; rr < 4; rr++) {
                if (rok[rr]) {
                    if (xin) {
                        r[rr][0] = __ldg(pl + ro[rr]);
                        r[rr][1] = __ldg(pl + ro[rr] + 1);
                        r[rr][2] = __ldg(pl + ro[rr] + 2);
                        r[rr][3] = __ldg(pl + ro[rr] + 3);
                    } else {
                        #pragma unroll
                        for (int c = 0; c < 4; c++)
                            r[rr][c] = cok[c] ? __ldg(pl + ro[rr] + c) : 0.0f;
                    }
                } else {
                    r[rr][0] = r[rr][1] = r[rr][2] = r[rr][3] = 0.0f;
                }
            }
        }

        // ---- element GEMM: all-LDS inner loop ----
        #pragma unroll
        for (int ciq = 0; ciq < 8; ciq++) {
            float Vv[8];
            #pragma unroll
            for (int i = 0; i < 8; i++)
                Vv[i] = sV[(ciq * 16 + p) * 33 + tq * 8 + i];
            const float* Up = sU + (ciq * 16 + p) * 25 + cg * 6;
            float Uu[6];
            #pragma unroll
            for (int c = 0; c < 6; c++) Uu[c] = Up[c];
            #pragma unroll
            for (int c = 0; c < 6; c++)
                #pragma unroll
                for (int i = 0; i < 8; i++)
                    acc[i][c] = fmaf(Vv[i], Uu[c], acc[i][c]);
        }
    }

    // ---- two-pass epilogue: Y = At M A, bias, stores ----
    #pragma unroll
    for (int pp = 0; pp < 2; pp++) {
        __syncthreads();
        if ((cg >> 1) == pp) {
            #pragma unroll
            for (int i = 0; i < 8; i++)
                #pragma unroll
                for (int c = 0; c < 6; c++)
                    sM[((tq * 8 + i) * 12 + (cg & 1) * 6 + c) * 18 + p] = acc[i][c];
        }
        __syncthreads();

        if (tid < 192) {
            int tile = tid & 31;
            int cop = tid >> 5;              // 0..5
            int tx = tile & 7, ty = tile >> 3;
            int gx = bx * 16 + tx * 2;
            int gy = by * 8 + ty * 2;
            int pix = gy * WW + gx;

            float y2[2][2][2];
            #pragma unroll
            for (int s = 0; s < 2; s++) {
                int col = cop * 2 + s;       // local 0..11
                int co = pp * 12 + col;
                float m[16];
                #pragma unroll
                for (int q = 0; q < 16; q++) m[q] = sM[(tile * 12 + col) * 18 + q];
                float r0[4], r1[4];
                #pragma unroll
                for (int j = 0; j < 4; j++) {
                    r0[j] = m[j] + m[4 + j] + m[8 + j];
                    r1[j] = m[4 + j] - m[8 + j] - m[12 + j];
                }
                float bv = __ldg(bias + co);
                y2[s][0][0] = r0[0] + r0[1] + r0[2] + bv;
                y2[s][0][1] = r0[1] - r0[2] - r0[3] + bv;
                y2[s][1][0] = r1[0] + r1[1] + r1[2] + bv;
                y2[s][1][1] = r1[1] - r1[2] - r1[3] + bv;

                if (co >= 16) {
                    float* oa = g_oa + ((size_t)b * COUT + co) * HWP + pix;
                    oa[0] = y2[s][0][0]; oa[1] = y2[s][0][1];
                    oa[WW] = y2[s][1][0]; oa[WW + 1] = y2[s][1][1];
                } else {
                    int oc = (co < 8) ? co : co + 2;
                    float* o = out + ((size_t)b * 18 + oc) * HWP + pix;
                    o[0] = y2[s][0][0]; o[1] = y2[s][0][1];
                    o[WW] = y2[s][1][0]; o[WW + 1] = y2[s][1][1];
                }
            }
            int co0g = pp * 12 + cop * 2;
            if (co0g < 16) {
                float2* op = g_off2 + ((size_t)b * NUMK + (co0g >> 1)) * HWP + pix;
                op[0]      = make_float2(y2[0][0][0], y2[1][0][0]);
                op[1]      = make_float2(y2[0][0][1], y2[1][0][1]);
                op[WW]     = make_float2(y2[0][1][0], y2[1][1][0]);
                op[WW + 1] = make_float2(y2[0][1][1], y2[1][1][1]);
            }
        }
    }
}

// ============================================================================
// Kernel 4: fused cos-affinity + confidence + TGASS + softmax.
// ============================================================================
__global__ void fused_kernel(const float* __restrict__ gtconf,
                             const float* __restrict__ ascp,
                             float* __restrict__ out) {
    int Xg = blockIdx.x * 256 + threadIdx.x;
    int b = Xg / (8 * HWP);
    int X = Xg - b * (8 * HWP);
    int c = X / HWP;
    int P2 = X - c * HWP;
    int P = X >> 3;
    int m = X & 7;
    int i2 = P2 / WW, j2 = P2 - i2 * WW;

    const float2* off_b = g_off2 + (size_t)b * NUMK * HWP;
    const float*  oa_b  = g_oa + (size_t)b * COUT * HWP;
    const float*  feac  = g_fea + ((size_t)b * 8 + c) * HWP;
    float fv = g_feahwc[((size_t)b * HWP + P) * 8 + m];

    float v[8];
    #pragma unroll
    for (int k = 0; k < 8; k++) {
        float2 o = off_b[(size_t)k * HWP + P2];        // (dy, dx)
        float base = (k < 4) ? (float)i2 : (float)j2;  // faithful to ref's repeat bug
        v[k] = fv * bilin0(feac, o.x + base, o.y + base, HH, WW);
    }

    int l = threadIdx.x & 31;
    #pragma unroll
    for (int d = 4; d >= 1; d >>= 1) {
        #pragma unroll
        for (int k = 0; k < 8; k++) {
            float o = __shfl_xor_sync(0xffffffffu, v[k], d);
            if (((k ^ l) & d) == 0) v[k] += o;
        }
    }
    float cw = v[m];

    int i = P / WW, j = P - i * WW;
    float araw = oa_b[(size_t)(16 + m) * HWP + P];
    float2 od = off_b[(size_t)m * HWP + P];            // (dy, dx)
    const float* gc = gtconf + (size_t)b * HWP;
    float conf = bilin0(gc, od.y + (float)j, od.x + (float)i, HH, WW);

    float asc = __ldg(ascp);
    float aff = __fdividef(tanh_fast(araw * cw), asc + 1e-8f);
    aff = aff * conf;

    float s = fabsf(aff);
    s += __shfl_xor_sync(0xffffffffu, s, 1);
    s += __shfl_xor_sync(0xffffffffu, s, 2);
    s += __shfl_xor_sync(0xffffffffu, s, 4);
    float denom = fmaxf(s + 1e-4f, 1.0f);
    float an = __fdividef(aff, denom);

    float t = an;
    t += __shfl_xor_sync(0xffffffffu, t, 1);
    t += __shfl_xor_sync(0xffffffffu, t, 2);
    t += __shfl_xor_sync(0xffffffffu, t, 4);
    float ref = 1.0f - t;

    float mx = an;
    mx = fmaxf(mx, __shfl_xor_sync(0xffffffffu, mx, 1));
    mx = fmaxf(mx, __shfl_xor_sync(0xffffffffu, mx, 2));
    mx = fmaxf(mx, __shfl_xor_sync(0xffffffffu, mx, 4));
    mx = fmaxf(mx, ref);

    float e  = __expf(an - mx);
    float er = __expf(ref - mx);
    float se = e;
    se += __shfl_xor_sync(0xffffffffu, se, 1);
    se += __shfl_xor_sync(0xffffffffu, se, 2);
    se += __shfl_xor_sync(0xffffffffu, se, 4);
    se += er;
    float inv = __fdividef(1.0f, se);

    float* outa = out + (size_t)BB * 18 * HWP + (size_t)b * 9 * HWP;
    int oc = (m < 4) ? m : m + 1;
    outa[(size_t)oc * HWP + P] = e * inv;
    if (m == 0) outa[(size_t)4 * HWP + P] = er * inv;
}

// ============================================================================
extern "C" void kernel_launch(void* const* d_in, const int* in_sizes, int n_in,
                              void* d_out, int out_size) {
    const float* guidance = (const float*)d_in[0];
    const float* gtconf   = (const float*)d_in[1];
    const float* tgt      = (const float*)d_in[2];
    const float* convw    = (const float*)d_in[3];
    const float* convb    = (const float*)d_in[4];
    const float* asc      = (const float*)d_in[5];
    float* out = (float*)d_out;

    cudaFuncSetAttribute(conv_wino_kernel,
                         cudaFuncAttributeMaxDynamicSharedMemorySize, WINO_SMEM);

    upsample_kernel<<<(BB * HWP + 255) / 256, 256>>>(tgt, out);
    wino_weights_kernel<<<(CIN * COUT + 255) / 256, 256>>>(convw);
    conv_wino_kernel<<<dim3(WW / 16, HH / 8, BB), 256, WINO_SMEM>>>(guidance, convb, out);
    fused_kernel<<<(BB * 8 * HWP) / 256, 256>>>(gtconf, asc, out);
}

// round 14
// speedup vs baseline: 1.4404x; 1.0404x over previous
#include <cuda_runtime.h>
#include <math.h>

#define HH 240
#define WW 320
#define HWP (HH*WW)
#define BB 4
#define CIN 64
#define COUT 24
#define HS 120
#define WS 160
#define NUMK 8

// ---- scratch (static device globals: allowed; no allocation) ----
__device__ float  g_oa[BB*COUT*HWP];     // conv output (only ch 16..23 aff_raw consumed by fused)
__device__ float2 g_off2[BB*NUMK*HWP];   // packed offsets: [b][k][P] = (dy, dx)
__device__ float  g_fea[BB*8*HWP];       // upsampled features CHW
__device__ float  g_feahwc[BB*HWP*8];    // upsampled features HWC
__device__ float  g_U[CIN*16*25];        // Winograd weights, PRE-PADDED stride-25 rows [ci*16+p][25]

__device__ __forceinline__ float tanh_fast(float x) {
    float y;
    asm("tanh.approx.f32 %0, %1;" : "=f"(y) : "f"(x));
    return y;
}

// ============================================================================
// bilinear with zeros padding (matches reference _bilinear_zeros)
// ============================================================================
__device__ __forceinline__ float bilin0(const float* __restrict__ img, float x, float y,
                                        int Hi, int Wi) {
    float xf = floorf(x), yf = floorf(y);
    float wx = x - xf, wy = y - yf;
    int x0 = (int)xf, y0 = (int)yf;
    int x1 = x0 + 1, y1 = y0 + 1;

    bool xv0 = (x0 >= 0) && (x0 <= Wi - 1);
    bool xv1 = (x1 >= 0) && (x1 <= Wi - 1);
    bool yv0 = (y0 >= 0) && (y0 <= Hi - 1);
    bool yv1 = (y1 >= 0) && (y1 <= Hi - 1);

    int xc0 = min(max(x0, 0), Wi - 1);
    int xc1 = min(max(x1, 0), Wi - 1);
    int yc0 = min(max(y0, 0), Hi - 1);
    int yc1 = min(max(y1, 0), Hi - 1);

    float v00 = (xv0 && yv0) ? img[yc0 * Wi + xc0] : 0.0f;
    float v10 = (xv1 && yv0) ? img[yc0 * Wi + xc1] : 0.0f;
    float v01 = (xv0 && yv1) ? img[yc1 * Wi + xc0] : 0.0f;
    float v11 = (xv1 && yv1) ? img[yc1 * Wi + xc1] : 0.0f;

    return v00 * ((1.0f - wy) * (1.0f - wx))
         + v10 * ((1.0f - wy) * wx)
         + v01 * (wy * (1.0f - wx))
         + v11 * (wy * wx);
}

// ============================================================================
// Kernel 1: 2x bilinear upsample + zero ch 8/9 of offset_full.
// ============================================================================
__global__ void upsample_kernel(const float* __restrict__ tgt, float* __restrict__ out) {
    int idx = blockIdx.x * blockDim.x + threadIdx.x;
    if (idx >= BB * HWP) return;
    int b = idx / HWP;
    int P = idx - b * HWP;
    int y = P / WW, x = P - (P / WW) * WW;

    out[((size_t)b * 18 + 8) * HWP + P] = 0.0f;
    out[((size_t)b * 18 + 9) * HWP + P] = 0.0f;

    int ty = y >> 1, tx = x >> 1;
    int y0, y1, x0, x1;
    float wy0, wy1, wx0, wx1;
    if (y & 1) { y0 = ty; y1 = min(ty + 1, HS - 1); wy0 = 0.75f; wy1 = 0.25f; }
    else       { y0 = max(ty - 1, 0); y1 = ty;      wy0 = 0.25f; wy1 = 0.75f; }
    if (x & 1) { x0 = tx; x1 = min(tx + 1, WS - 1); wx0 = 0.75f; wx1 = 0.25f; }
    else       { x0 = max(tx - 1, 0); x1 = tx;      wx0 = 0.25f; wx1 = 0.75f; }

    const float* base = tgt + b * 8 * HS * WS;
    float vv[8];
    #pragma unroll
    for (int c = 0; c < 8; c++) {
        const float* pl = base + c * HS * WS;
        float r0 = wx0 * pl[y0 * WS + x0] + wx1 * pl[y0 * WS + x1];
        float r1 = wx0 * pl[y1 * WS + x0] + wx1 * pl[y1 * WS + x1];
        float v = wy0 * r0 + wy1 * r1;
        g_fea[(b * 8 + c) * HWP + P] = v;
        vv[c] = v;
    }
    float4* dst = (float4*)(g_feahwc + ((size_t)b * HWP + P) * 8);
    dst[0] = make_float4(vv[0], vv[1], vv[2], vv[3]);
    dst[1] = make_float4(vv[4], vv[5], vv[6], vv[7]);
}

// ============================================================================
// Kernel 2: Winograd F(2,3) weight transform U = G g G^T
// -> g_U rows pre-padded to 25 so conv staging is identity-indexed.
// ============================================================================
__global__ void wino_weights_kernel(const float* __restrict__ wgt) {
    int t = blockIdx.x * blockDim.x + threadIdx.x;
    if (t >= CIN * COUT) return;
    int ci = t / COUT;
    int co = t - ci * COUT;

    float g[9];
    #pragma unroll
    for (int r = 0; r < 9; r++) g[r] = __ldg(wgt + ((size_t)co * CIN + ci) * 9 + r);

    float q[4][3];
    #pragma unroll
    for (int c = 0; c < 3; c++) {
        float g0 = g[c], g1 = g[3 + c], g2 = g[6 + c];
        q[0][c] = g0;
        q[1][c] = 0.5f * (g0 + g1 + g2);
        q[2][c] = 0.5f * (g0 - g1 + g2);
        q[3][c] = g2;
    }
    #pragma unroll
    for (int i = 0; i < 4; i++) {
        float v0 = q[i][0], v1 = q[i][1], v2 = q[i][2];
        g_U[(ci * 16 + i * 4 + 0) * 25 + co] = v0;
        g_U[(ci * 16 + i * 4 + 1) * 25 + co] = 0.5f * (v0 + v1 + v2);
        g_U[(ci * 16 + i * 4 + 2) * 25 + co] = 0.5f * (v0 - v1 + v2);
        g_U[(ci * 16 + i * 4 + 3) * 25 + co] = v2;
    }
}

// ============================================================================
// Kernel 3: Winograd F(2x2,3x3) conv 64->24 + bias. Fully software-pipelined:
// BOTH the raw 4x4 guidance tile AND the U slab (13 regs, identity-indexed
// thanks to pre-padded g_U) for group g+1 are loaded into registers during the
// GEMM of group g. The barrier window contains only STS.
// sV stride 36 -> Vv fetched as 2x LDS.128.
// smem: sV[8*16*36] + max(sM[32*12*18], sU[8*16*25]) = 45.6 KB
// ============================================================================
#define SV_ELEMS (8*16*36)
#define SM_ELEMS (32*12*18)
#define USLAB    (8*16*25)          // 3200 = 12*256 + 128
#define WINO_SMEM ((SV_ELEMS + SM_ELEMS) * 4)

__global__ __launch_bounds__(256, 2) void conv_wino_kernel(
    const float* __restrict__ gin, const float* __restrict__ bias,
    float* __restrict__ out) {
    extern __shared__ float smem[];
    float* sV = smem;               // [ciq][p][tile] stride 36
    float* sM = smem + SV_ELEMS;    // epilogue: [tile][co12][p(18)]
    float* sU = smem + SV_ELEMS;    // mainloop: [ciq*16+p][co(25)]  (aliases sM)

    int tid = threadIdx.x;
    int p  = tid & 15;
    int cg = (tid >> 4) & 3;
    int tq = tid >> 6;
    int bx = blockIdx.x, by = blockIdx.y, b = blockIdx.z;

    float acc[8][6];
    #pragma unroll
    for (int i = 0; i < 8; i++)
        #pragma unroll
        for (int c = 0; c < 6; c++) acc[i][c] = 0.0f;

    const float* gb = gin + (size_t)b * CIN * HWP;

    // transform-task coords (one (tile, ci) per thread)
    int ttile = tid & 31;
    int tciq  = tid >> 5;
    int ttx = ttile & 7, tty = ttile >> 3;
    int tgx0 = bx * 16 + ttx * 2 - 1;
    int tgy0 = by * 8 + tty * 2 - 1;
    bool xin = (tgx0 >= 0 && tgx0 + 3 < WW);

    int ro[4];
    bool rok[4];
    bool cok[4];
    #pragma unroll
    for (int rr = 0; rr < 4; rr++) {
        int yy = tgy0 + rr;
        rok[rr] = (yy >= 0 && yy < HH);
        ro[rr] = yy * WW + tgx0;
    }
    #pragma unroll
    for (int c = 0; c < 4; c++) {
        int xx = tgx0 + c;
        cok[c] = (xx >= 0 && xx < WW);
    }

    bool utail = (tid < USLAB - 12 * 256);   // last partial chunk

    // ---- prologue prefetch: guidance + U slab for group 0 ----
    float r[4][4];
    float ureg[13];
    {
        const float* pl = gb + (size_t)tciq * HWP;
        #pragma unroll
        for (int rr = 0; rr < 4; rr++) {
            if (rok[rr]) {
                if (xin) {
                    r[rr][0] = __ldg(pl + ro[rr]);
                    r[rr][1] = __ldg(pl + ro[rr] + 1);
                    r[rr][2] = __ldg(pl + ro[rr] + 2);
                    r[rr][3] = __ldg(pl + ro[rr] + 3);
                } else {
                    #pragma unroll
                    for (int c = 0; c < 4; c++)
                        r[rr][c] = cok[c] ? __ldg(pl + ro[rr] + c) : 0.0f;
                }
            } else {
                r[rr][0] = r[rr][1] = r[rr][2] = r[rr][3] = 0.0f;
            }
        }
        const float* us = g_U;               // group 0
        #pragma unroll
        for (int k = 0; k < 12; k++) ureg[k] = __ldg(us + tid + k * 256);
        ureg[12] = utail ? __ldg(us + tid + 12 * 256) : 0.0f;
    }

    for (int g8 = 0; g8 < 8; g8++) {
        // ---- fold raw rows -> e (ALU only) ----
        float e0[4], e1[4], e2[4], e3[4];
        #pragma unroll
        for (int c = 0; c < 4; c++) {
            e0[c] = r[0][c] - r[2][c];
            e1[c] = r[1][c] + r[2][c];
            e2[c] = r[2][c] - r[1][c];
            e3[c] = r[1][c] - r[3][c];
        }

        __syncthreads();   // GEMM of g8-1 done reading sV/sU

        // ---- window: pure STS ----
        {
            float* svb = sV + tciq * 16 * 36 + ttile;
            #pragma unroll
            for (int i = 0; i < 4; i++) {
                const float* er = (i == 0) ? e0 : (i == 1) ? e1 : (i == 2) ? e2 : e3;
                svb[(i * 4 + 0) * 36] = er[0] - er[2];
                svb[(i * 4 + 1) * 36] = er[1] + er[2];
                svb[(i * 4 + 2) * 36] = er[2] - er[1];
                svb[(i * 4 + 3) * 36] = er[1] - er[3];
            }
            #pragma unroll
            for (int k = 0; k < 12; k++) sU[tid + k * 256] = ureg[k];
            if (utail) sU[tid + 12 * 256] = ureg[12];
        }
        __syncthreads();

        // ---- issue prefetch for group g8+1 (in flight during GEMM) ----
        if (g8 < 7) {
            const float* pl = gb + (size_t)((g8 + 1) * 8 + tciq) * HWP;
            #pragma unroll
            for (int rr = 0; rr < 4; rr++) {
                if (rok[rr]) {
                    if (xin) {
                        r[rr][0] = __ldg(pl + ro[rr]);
                        r[rr][1] = __ldg(pl + ro[rr] + 1);
                        r[rr][2] = __ldg(pl + ro[rr] + 2);
                        r[rr][3] = __ldg(pl + ro[rr] + 3);
                    } else {
                        #pragma unroll
                        for (int c = 0; c < 4; c++)
                            r[rr][c] = cok[c] ? __ldg(pl + ro[rr] + c) : 0.0f;
                    }
                } else {
                    r[rr][0] = r[rr][1] = r[rr][2] = r[rr][3] = 0.0f;
                }
            }
            const float* us = g_U + (g8 + 1) * USLAB;
            #pragma unroll
            for (int k = 0; k < 12; k++) ureg[k] = __ldg(us + tid + k * 256);
            ureg[12] = utail ? __ldg(us + tid + 12 * 256) : 0.0f;
        }

        // ---- element GEMM: vectorized V reads + scalar U reads ----
        #pragma unroll
        for (int ciq = 0; ciq < 8; ciq++) {
            const float* vb = sV + (ciq * 16 + p) * 36 + tq * 8;
            float4 va = *(const float4*)(vb);
            float4 vb4 = *(const float4*)(vb + 4);
            float Vv[8] = {va.x, va.y, va.z, va.w, vb4.x, vb4.y, vb4.z, vb4.w};
            const float* Up = sU + (ciq * 16 + p) * 25 + cg * 6;
            float Uu[6];
            #pragma unroll
            for (int c = 0; c < 6; c++) Uu[c] = Up[c];
            #pragma unroll
            for (int c = 0; c < 6; c++)
                #pragma unroll
                for (int i = 0; i < 8; i++)
                    acc[i][c] = fmaf(Vv[i], Uu[c], acc[i][c]);
        }
    }

    // ---- two-pass epilogue: Y = At M A, bias, stores ----
    #pragma unroll
    for (int pp = 0; pp < 2; pp++) {
        __syncthreads();
        if ((cg >> 1) == pp) {
            #pragma unroll
            for (int i = 0; i < 8; i++)
                #pragma unroll
                for (int c = 0; c < 6; c++)
                    sM[((tq * 8 + i) * 12 + (cg & 1) * 6 + c) * 18 + p] = acc[i][c];
        }
        __syncthreads();

        if (tid < 192) {
            int tile = tid & 31;
            int cop = tid >> 5;              // 0..5
            int tx = tile & 7, ty = tile >> 3;
            int gx = bx * 16 + tx * 2;
            int gy = by * 8 + ty * 2;
            int pix = gy * WW + gx;

            float y2[2][2][2];
            #pragma unroll
            for (int s = 0; s < 2; s++) {
                int col = cop * 2 + s;       // local 0..11
                int co = pp * 12 + col;
                float m[16];
                #pragma unroll
                for (int q = 0; q < 16; q++) m[q] = sM[(tile * 12 + col) * 18 + q];
                float r0[4], r1[4];
                #pragma unroll
                for (int j = 0; j < 4; j++) {
                    r0[j] = m[j] + m[4 + j] + m[8 + j];
                    r1[j] = m[4 + j] - m[8 + j] - m[12 + j];
                }
                float bv = __ldg(bias + co);
                y2[s][0][0] = r0[0] + r0[1] + r0[2] + bv;
                y2[s][0][1] = r0[1] - r0[2] - r0[3] + bv;
                y2[s][1][0] = r1[0] + r1[1] + r1[2] + bv;
                y2[s][1][1] = r1[1] - r1[2] - r1[3] + bv;

                if (co >= 16) {
                    float* oa = g_oa + ((size_t)b * COUT + co) * HWP + pix;
                    oa[0] = y2[s][0][0]; oa[1] = y2[s][0][1];
                    oa[WW] = y2[s][1][0]; oa[WW + 1] = y2[s][1][1];
                } else {
                    int oc = (co < 8) ? co : co + 2;
                    float* o = out + ((size_t)b * 18 + oc) * HWP + pix;
                    o[0] = y2[s][0][0]; o[1] = y2[s][0][1];
                    o[WW] = y2[s][1][0]; o[WW + 1] = y2[s][1][1];
                }
            }
            int co0g = pp * 12 + cop * 2;
            if (co0g < 16) {
                float2* op = g_off2 + ((size_t)b * NUMK + (co0g >> 1)) * HWP + pix;
                op[0]      = make_float2(y2[0][0][0], y2[1][0][0]);
                op[1]      = make_float2(y2[0][0][1], y2[1][0][1]);
                op[WW]     = make_float2(y2[0][1][0], y2[1][1][0]);
                op[WW + 1] = make_float2(y2[0][1][1], y2[1][1][1]);
            }
        }
    }
}

// ============================================================================
// Kernel 4: fused cos-affinity + confidence + TGASS + softmax.
// ============================================================================
__global__ void fused_kernel(const float* __restrict__ gtconf,
                             const float* __restrict__ ascp,
                             float* __restrict__ out) {
    int Xg = blockIdx.x * 256 + threadIdx.x;
    int b = Xg / (8 * HWP);
    int X = Xg - b * (8 * HWP);
    int c = X / HWP;
    int P2 = X - c * HWP;
    int P = X >> 3;
    int m = X & 7;
    int i2 = P2 / WW, j2 = P2 - i2 * WW;

    const float2* off_b = g_off2 + (size_t)b * NUMK * HWP;
    const float*  oa_b  = g_oa + (size_t)b * COUT * HWP;
    const float*  feac  = g_fea + ((size_t)b * 8 + c) * HWP;
    float fv = g_feahwc[((size_t)b * HWP + P) * 8 + m];

    float v[8];
    #pragma unroll
    for (int k = 0; k < 8; k++) {
        float2 o = off_b[(size_t)k * HWP + P2];        // (dy, dx)
        float base = (k < 4) ? (float)i2 : (float)j2;  // faithful to ref's repeat bug
        v[k] = fv * bilin0(feac, o.x + base, o.y + base, HH, WW);
    }

    int l = threadIdx.x & 31;
    #pragma unroll
    for (int d = 4; d >= 1; d >>= 1) {
        #pragma unroll
        for (int k = 0; k < 8; k++) {
            float o = __shfl_xor_sync(0xffffffffu, v[k], d);
            if (((k ^ l) & d) == 0) v[k] += o;
        }
    }
    float cw = v[m];

    int i = P / WW, j = P - i * WW;
    float araw = oa_b[(size_t)(16 + m) * HWP + P];
    float2 od = off_b[(size_t)m * HWP + P];            // (dy, dx)
    const float* gc = gtconf + (size_t)b * HWP;
    float conf = bilin0(gc, od.y + (float)j, od.x + (float)i, HH, WW);

    float asc = __ldg(ascp);
    float aff = __fdividef(tanh_fast(araw * cw), asc + 1e-8f);
    aff = aff * conf;

    float s = fabsf(aff);
    s += __shfl_xor_sync(0xffffffffu, s, 1);
    s += __shfl_xor_sync(0xffffffffu, s, 2);
    s += __shfl_xor_sync(0xffffffffu, s, 4);
    float denom = fmaxf(s + 1e-4f, 1.0f);
    float an = __fdividef(aff, denom);

    float t = an;
    t += __shfl_xor_sync(0xffffffffu, t, 1);
    t += __shfl_xor_sync(0xffffffffu, t, 2);
    t += __shfl_xor_sync(0xffffffffu, t, 4);
    float ref = 1.0f - t;

    float mx = an;
    mx = fmaxf(mx, __shfl_xor_sync(0xffffffffu, mx, 1));
    mx = fmaxf(mx, __shfl_xor_sync(0xffffffffu, mx, 2));
    mx = fmaxf(mx, __shfl_xor_sync(0xffffffffu, mx, 4));
    mx = fmaxf(mx, ref);

    float e  = __expf(an - mx);
    float er = __expf(ref - mx);
    float se = e;
    se += __shfl_xor_sync(0xffffffffu, se, 1);
    se += __shfl_xor_sync(0xffffffffu, se, 2);
    se += __shfl_xor_sync(0xffffffffu, se, 4);
    se += er;
    float inv = __fdividef(1.0f, se);

    float* outa = out + (size_t)BB * 18 * HWP + (size_t)b * 9 * HWP;
    int oc = (m < 4) ? m : m + 1;
    outa[(size_t)oc * HWP + P] = e * inv;
    if (m == 0) outa[(size_t)4 * HWP + P] = er * inv;
}

// ============================================================================
extern "C" void kernel_launch(void* const* d_in, const int* in_sizes, int n_in,
                              void* d_out, int out_size) {
    const float* guidance = (const float*)d_in[0];
    const float* gtconf   = (const float*)d_in[1];
    const float* tgt      = (const float*)d_in[2];
    const float* convw    = (const float*)d_in[3];
    const float* convb    = (const float*)d_in[4];
    const float* asc      = (const float*)d_in[5];
    float* out = (float*)d_out;

    cudaFuncSetAttribute(conv_wino_kernel,
                         cudaFuncAttributeMaxDynamicSharedMemorySize, WINO_SMEM);

    upsample_kernel<<<(BB * HWP + 255) / 256, 256>>>(tgt, out);
    wino_weights_kernel<<<(CIN * COUT + 255) / 256, 256>>>(convw);
    conv_wino_kernel<<<dim3(WW / 16, HH / 8, BB), 256, WINO_SMEM>>>(guidance, convb, out);
    fused_kernel<<<(BB * 8 * HWP) / 256, 256>>>(gtconf, asc, out);
}